// round 1
// baseline (speedup 1.0000x reference)
#include <cuda_runtime.h>

// Problem constants
#define B_SZ 2
#define S_SZ 2048
#define D_SZ 1024
#define H_SZ 16
#define DK_SZ 64
#define M_SZ (B_SZ * S_SZ)   // 4096 rows for projection GEMMs

// Scratch (device globals; no runtime allocation allowed)
__device__ float g_Q[B_SZ * H_SZ * S_SZ * DK_SZ];
__device__ float g_K[B_SZ * H_SZ * S_SZ * DK_SZ];
__device__ float g_V[B_SZ * H_SZ * S_SZ * DK_SZ];
__device__ float g_C[B_SZ * S_SZ * D_SZ];

// ---------------------------------------------------------------------------
// GEMM: out[m][n] = (sum_k A[m][k] * W[n][k] + bias[n]) * scale
// A: [M=4096, K=1024] row-major; W: [N=1024, K=1024] row-major (torch Linear)
// head_layout=1 -> write to [B,H,S,dk] layout; else plain [M,N].
// Tiling: 64x64 block tile, BK=16, 256 threads, 4x4 per thread.
// ---------------------------------------------------------------------------
__global__ __launch_bounds__(256) void gemm_bias_kernel(
    const float* __restrict__ A, const float* __restrict__ W,
    const float* __restrict__ bias, float* __restrict__ out,
    float scale, int head_layout)
{
    __shared__ float At[16][68];  // [k][m] transposed
    __shared__ float Wt[16][68];  // [k][n] transposed

    const int tid = threadIdx.x;
    const int tx = tid & 15;
    const int ty = tid >> 4;
    const int m0 = blockIdx.y * 64;
    const int n0 = blockIdx.x * 64;

    const float* Ap = A + (size_t)m0 * D_SZ;
    const float* Wp = W + (size_t)n0 * D_SZ;

    float acc[4][4] = {};

    const int lr = tid >> 2;         // 0..63
    const int lc4 = (tid & 3) << 2;  // 0,4,8,12

    for (int k0 = 0; k0 < D_SZ; k0 += 16) {
        float4 a = *(const float4*)&Ap[lr * D_SZ + k0 + lc4];
        At[lc4 + 0][lr] = a.x;
        At[lc4 + 1][lr] = a.y;
        At[lc4 + 2][lr] = a.z;
        At[lc4 + 3][lr] = a.w;
        float4 w = *(const float4*)&Wp[lr * D_SZ + k0 + lc4];
        Wt[lc4 + 0][lr] = w.x;
        Wt[lc4 + 1][lr] = w.y;
        Wt[lc4 + 2][lr] = w.z;
        Wt[lc4 + 3][lr] = w.w;
        __syncthreads();

#pragma unroll
        for (int kk = 0; kk < 16; kk++) {
            float4 a4 = *(const float4*)&At[kk][ty * 4];
            float4 b4 = *(const float4*)&Wt[kk][tx * 4];
            float av[4] = {a4.x, a4.y, a4.z, a4.w};
            float bv[4] = {b4.x, b4.y, b4.z, b4.w};
#pragma unroll
            for (int i = 0; i < 4; i++)
#pragma unroll
                for (int j = 0; j < 4; j++)
                    acc[i][j] += av[i] * bv[j];
        }
        __syncthreads();
    }

#pragma unroll
    for (int i = 0; i < 4; i++) {
        const int m = m0 + ty * 4 + i;
#pragma unroll
        for (int j = 0; j < 4; j++) {
            const int n = n0 + tx * 4 + j;
            float v = (acc[i][j] + bias[n]) * scale;
            if (head_layout) {
                const int b = m >> 11;         // m / 2048
                const int s = m & 2047;
                const int h = n >> 6;          // n / 64
                const int dh = n & 63;
                out[((((size_t)b << 4) + h) * S_SZ + s) * DK_SZ + dh] = v;
            } else {
                out[(size_t)m * D_SZ + n] = v;
            }
        }
    }
}

// ---------------------------------------------------------------------------
// Flash attention: per (b, h, 64-query tile). Q pre-scaled by 1/sqrt(dk).
// Q/K/V layout: [B,H,S,dk]. Output C: [B,S,D] with head h at cols h*64..
// smem (dynamic): Qt[64][68] (d-major), Kt[64][68] (d-major),
//                 Vs[64][68] (c-major), Ps[64][68] (r-major). Total 69632 B.
// 256 threads = 16x16, each thread owns 4x4 of the 64x64 score / output tile.
// ---------------------------------------------------------------------------
__global__ __launch_bounds__(256) void flash_attn_kernel(
    const float* __restrict__ Q, const float* __restrict__ K,
    const float* __restrict__ V, float* __restrict__ C)
{
    extern __shared__ float sm[];
    float* Qt = sm;                 // [d][r]
    float* Kt = Qt + 64 * 68;       // [d][c]
    float* Vs = Kt + 64 * 68;       // [c][d]
    float* Ps = Vs + 64 * 68;       // [r][c]

    const int tid = threadIdx.x;
    const int tx = tid & 15;
    const int ty = tid >> 4;
    const int qt = blockIdx.x;      // query tile (32)
    const int h = blockIdx.y;       // head (16)
    const int b = blockIdx.z;       // batch (2)

    const size_t head_off = (((size_t)b * H_SZ + h) * S_SZ) * DK_SZ;
    const float* Qb = Q + head_off + (size_t)qt * 64 * DK_SZ;
    const float* Kb = K + head_off;
    const float* Vb = V + head_off;

    // Load Q tile transposed: Qt[d][r]
#pragma unroll
    for (int rep = 0; rep < 4; rep++) {
        int idx = rep * 256 + tid;
        int r = idx >> 4;
        int d4 = (idx & 15) << 2;
        float4 q = *(const float4*)&Qb[r * DK_SZ + d4];
        Qt[(d4 + 0) * 68 + r] = q.x;
        Qt[(d4 + 1) * 68 + r] = q.y;
        Qt[(d4 + 2) * 68 + r] = q.z;
        Qt[(d4 + 3) * 68 + r] = q.w;
    }

    float acc[4][4] = {};
    float mprev[4] = {-1e30f, -1e30f, -1e30f, -1e30f};
    float lsum[4] = {0.f, 0.f, 0.f, 0.f};

    for (int kt = 0; kt < S_SZ / 64; kt++) {
        // Load K tile transposed + V tile natural
#pragma unroll
        for (int rep = 0; rep < 4; rep++) {
            int idx = rep * 256 + tid;
            int r = idx >> 4;
            int d4 = (idx & 15) << 2;
            float4 k4 = *(const float4*)&Kb[(kt * 64 + r) * DK_SZ + d4];
            Kt[(d4 + 0) * 68 + r] = k4.x;
            Kt[(d4 + 1) * 68 + r] = k4.y;
            Kt[(d4 + 2) * 68 + r] = k4.z;
            Kt[(d4 + 3) * 68 + r] = k4.w;
            float4 v4 = *(const float4*)&Vb[(kt * 64 + r) * DK_SZ + d4];
            *(float4*)&Vs[r * 68 + d4] = v4;
        }
        __syncthreads();

        // Phase A: S = Q @ K^T (64-deep dot)
        float s[4][4] = {};
#pragma unroll 16
        for (int d = 0; d < 64; d++) {
            float4 a4 = *(const float4*)&Qt[d * 68 + ty * 4];
            float4 b4 = *(const float4*)&Kt[d * 68 + tx * 4];
            float av[4] = {a4.x, a4.y, a4.z, a4.w};
            float bv[4] = {b4.x, b4.y, b4.z, b4.w};
#pragma unroll
            for (int i = 0; i < 4; i++)
#pragma unroll
                for (int j = 0; j < 4; j++)
                    s[i][j] += av[i] * bv[j];
        }

        // Phase B: online softmax (row stats via width-16 shuffles)
        float mt[4], mnew[4], alpha[4], rs[4];
#pragma unroll
        for (int i = 0; i < 4; i++) {
            mt[i] = fmaxf(fmaxf(s[i][0], s[i][1]), fmaxf(s[i][2], s[i][3]));
        }
#pragma unroll
        for (int o = 1; o < 16; o <<= 1) {
#pragma unroll
            for (int i = 0; i < 4; i++)
                mt[i] = fmaxf(mt[i], __shfl_xor_sync(0xffffffffu, mt[i], o));
        }
#pragma unroll
        for (int i = 0; i < 4; i++) {
            mnew[i] = fmaxf(mprev[i], mt[i]);
            alpha[i] = __expf(mprev[i] - mnew[i]);
            mprev[i] = mnew[i];
            rs[i] = 0.f;
        }
        float p[4][4];
#pragma unroll
        for (int i = 0; i < 4; i++) {
#pragma unroll
            for (int j = 0; j < 4; j++) {
                p[i][j] = __expf(s[i][j] - mnew[i]);
                rs[i] += p[i][j];
            }
        }
#pragma unroll
        for (int o = 1; o < 16; o <<= 1) {
#pragma unroll
            for (int i = 0; i < 4; i++)
                rs[i] += __shfl_xor_sync(0xffffffffu, rs[i], o);
        }
#pragma unroll
        for (int i = 0; i < 4; i++) {
            lsum[i] = lsum[i] * alpha[i] + rs[i];
#pragma unroll
            for (int j = 0; j < 4; j++)
                acc[i][j] *= alpha[i];
            // stage P to smem (natural layout)
            *(float4*)&Ps[(ty * 4 + i) * 68 + tx * 4] =
                make_float4(p[i][0], p[i][1], p[i][2], p[i][3]);
        }
        __syncthreads();

        // Phase C: O += P @ V
#pragma unroll 8
        for (int c = 0; c < 64; c++) {
            float4 v4 = *(const float4*)&Vs[c * 68 + tx * 4];
            float vv[4] = {v4.x, v4.y, v4.z, v4.w};
#pragma unroll
            for (int i = 0; i < 4; i++) {
                float pi = Ps[(ty * 4 + i) * 68 + c];
#pragma unroll
                for (int j = 0; j < 4; j++)
                    acc[i][j] += pi * vv[j];
            }
        }
        __syncthreads();  // protect Kt/Vs/Ps before next tile load
    }

    // Write context: C[b, s, h*64 + n] = acc / l
#pragma unroll
    for (int i = 0; i < 4; i++) {
        const int srow = qt * 64 + ty * 4 + i;
        const float inv_l = 1.0f / lsum[i];
        float* crow = C + ((size_t)b * S_SZ + srow) * D_SZ + h * DK_SZ + tx * 4;
        crow[0] = acc[i][0] * inv_l;
        crow[1] = acc[i][1] * inv_l;
        crow[2] = acc[i][2] * inv_l;
        crow[3] = acc[i][3] * inv_l;
    }
}

// ---------------------------------------------------------------------------
// Launch
// Inputs (metadata order): query, key, value, Wq, bq, Wk, bk, Wv, bv, Wo, bo
// ---------------------------------------------------------------------------
extern "C" void kernel_launch(void* const* d_in, const int* in_sizes, int n_in,
                              void* d_out, int out_size)
{
    const float* q  = (const float*)d_in[0];
    const float* k  = (const float*)d_in[1];
    const float* v  = (const float*)d_in[2];
    const float* Wq = (const float*)d_in[3];
    const float* bq = (const float*)d_in[4];
    const float* Wk = (const float*)d_in[5];
    const float* bk = (const float*)d_in[6];
    const float* Wv = (const float*)d_in[7];
    const float* bv = (const float*)d_in[8];
    const float* Wo = (const float*)d_in[9];
    const float* bo = (const float*)d_in[10];
    float* out = (float*)d_out;

    float *gq, *gk, *gv, *gc;
    cudaGetSymbolAddress((void**)&gq, g_Q);
    cudaGetSymbolAddress((void**)&gk, g_K);
    cudaGetSymbolAddress((void**)&gv, g_V);
    cudaGetSymbolAddress((void**)&gc, g_C);

    const int SMEM_ATTN = 4 * 64 * 68 * sizeof(float);  // 69632 B
    cudaFuncSetAttribute(flash_attn_kernel,
                         cudaFuncAttributeMaxDynamicSharedMemorySize, SMEM_ATTN);

    dim3 gemm_grid(D_SZ / 64, M_SZ / 64);  // (16, 64)
    const float qscale = 0.125f;            // 1/sqrt(64)

    gemm_bias_kernel<<<gemm_grid, 256>>>(q, Wq, bq, gq, qscale, 1);
    gemm_bias_kernel<<<gemm_grid, 256>>>(k, Wk, bk, gk, 1.0f, 1);
    gemm_bias_kernel<<<gemm_grid, 256>>>(v, Wv, bv, gv, 1.0f, 1);

    dim3 attn_grid(S_SZ / 64, H_SZ, B_SZ);  // (32, 16, 2)
    flash_attn_kernel<<<attn_grid, 256, SMEM_ATTN>>>(gq, gk, gv, gc);

    gemm_bias_kernel<<<gemm_grid, 256>>>(gc, Wo, bo, out, 1.0f, 0);
}

// round 2
// speedup vs baseline: 3.2681x; 3.2681x over previous
#include <cuda_runtime.h>
#include <cstdint>

#define B_SZ 2
#define S_SZ 2048
#define D_SZ 1024
#define H_SZ 16
#define DK_SZ 64
#define M_SZ (B_SZ * S_SZ)

// Scratch (device globals; no runtime allocation allowed)
__device__ float g_Q[B_SZ * H_SZ * S_SZ * DK_SZ];
__device__ float g_K[B_SZ * H_SZ * S_SZ * DK_SZ];
__device__ float g_V[B_SZ * H_SZ * S_SZ * DK_SZ];
__device__ float g_C[B_SZ * S_SZ * D_SZ];

// ---------------------------------------------------------------------------
// tf32 helpers
// ---------------------------------------------------------------------------
__device__ __forceinline__ uint32_t f2t(float x) {
    uint32_t u;
    asm("cvt.rna.tf32.f32 %0, %1;" : "=r"(u) : "f"(x));
    return u;
}

__device__ __forceinline__ void mma_tf32(float c[4], const uint32_t a[4],
                                         const uint32_t b[2]) {
    asm volatile(
        "mma.sync.aligned.m16n8k8.row.col.f32.tf32.tf32.f32 "
        "{%0,%1,%2,%3}, {%4,%5,%6,%7}, {%8,%9}, {%0,%1,%2,%3};\n"
        : "+f"(c[0]), "+f"(c[1]), "+f"(c[2]), "+f"(c[3])
        : "r"(a[0]), "r"(a[1]), "r"(a[2]), "r"(a[3]), "r"(b[0]), "r"(b[1]));
}

// ---------------------------------------------------------------------------
// tf32 GEMM: out[m][n] = (sum_k A[m][k] * W[n][k] + bias[n]) * scale
// A: [M,1024] row-major; W: [1024,1024] row-major (torch Linear weight).
// CTA tile 128x128, BK=32, 8 warps (2m x 4n), warp tile 64x32 (4x4 mma tiles).
// smem stride 36 -> all fragment reads are (4g+t)%32 conflict-free.
// ---------------------------------------------------------------------------
#define GSTR 36
__global__ __launch_bounds__(256) void gemm_tf32(
    const float* __restrict__ A, const float* __restrict__ W,
    const float* __restrict__ bias, float* __restrict__ out,
    float scale, int head_layout)
{
    __shared__ uint32_t As[128 * GSTR];
    __shared__ uint32_t Bs[128 * GSTR];

    const int tid = threadIdx.x;
    const int lane = tid & 31, wid = tid >> 5;
    const int g = lane >> 2, t = lane & 3;
    const int warpM = wid & 1, warpN = wid >> 1;
    const int m0 = blockIdx.y * 128, n0 = blockIdx.x * 128;
    const int lrow = tid >> 3;          // 0..31
    const int lcol = (tid & 7) << 2;    // 0,4,...,28

    float acc[4][4][4] = {};

    for (int kb = 0; kb < D_SZ; kb += 32) {
#pragma unroll
        for (int p = 0; p < 4; p++) {
            int row = p * 32 + lrow;
            float4 a4 = *(const float4*)&A[(size_t)(m0 + row) * D_SZ + kb + lcol];
            uint4 ua = {f2t(a4.x), f2t(a4.y), f2t(a4.z), f2t(a4.w)};
            *(uint4*)&As[row * GSTR + lcol] = ua;
            float4 b4 = *(const float4*)&W[(size_t)(n0 + row) * D_SZ + kb + lcol];
            uint4 ub = {f2t(b4.x), f2t(b4.y), f2t(b4.z), f2t(b4.w)};
            *(uint4*)&Bs[row * GSTR + lcol] = ub;
        }
        __syncthreads();

#pragma unroll
        for (int ks = 0; ks < 4; ks++) {
            uint32_t af[4][4], bf[4][2];
#pragma unroll
            for (int mt = 0; mt < 4; mt++) {
                int rb = warpM * 64 + mt * 16;
                af[mt][0] = As[(rb + g) * GSTR + ks * 8 + t];
                af[mt][1] = As[(rb + g + 8) * GSTR + ks * 8 + t];
                af[mt][2] = As[(rb + g) * GSTR + ks * 8 + t + 4];
                af[mt][3] = As[(rb + g + 8) * GSTR + ks * 8 + t + 4];
            }
#pragma unroll
            for (int nt = 0; nt < 4; nt++) {
                int nb = warpN * 32 + nt * 8 + g;
                bf[nt][0] = Bs[nb * GSTR + ks * 8 + t];
                bf[nt][1] = Bs[nb * GSTR + ks * 8 + t + 4];
            }
#pragma unroll
            for (int mt = 0; mt < 4; mt++)
#pragma unroll
                for (int nt = 0; nt < 4; nt++)
                    mma_tf32(acc[mt][nt], af[mt], bf[nt]);
        }
        __syncthreads();
    }

    // Epilogue: bias + scale; optional [B,H,S,dk] head layout
#pragma unroll
    for (int mt = 0; mt < 4; mt++) {
#pragma unroll
        for (int nt = 0; nt < 4; nt++) {
            int col = n0 + warpN * 32 + nt * 8 + 2 * t;
            float b0 = bias[col], b1 = bias[col + 1];
#pragma unroll
            for (int rr = 0; rr < 2; rr++) {
                int m = m0 + warpM * 64 + mt * 16 + g + rr * 8;
                float v0 = (acc[mt][nt][rr * 2 + 0] + b0) * scale;
                float v1 = (acc[mt][nt][rr * 2 + 1] + b1) * scale;
                if (head_layout) {
                    int bb = m >> 11, s = m & 2047, h = col >> 6, dh = col & 63;
                    float* o = &out[((((size_t)bb << 4) + h) * S_SZ + s) * DK_SZ + dh];
                    o[0] = v0;
                    o[1] = v1;
                } else {
                    float* o = &out[(size_t)m * D_SZ + col];
                    o[0] = v0;
                    o[1] = v1;
                }
            }
        }
    }
}

// ---------------------------------------------------------------------------
// Flash attention, tf32 mma. One CTA per (b, h, 64-query tile). 4 warps,
// each owns 16 score rows x 64 cols. Q pre-scaled by 1/sqrt(dk).
// smem (tf32/u32): Qs[64][68], Ks[64][68], Vs[64][72], Ps[64][68].
// Chosen strides make every fragment read bank-conflict-free.
// ---------------------------------------------------------------------------
#define QSTR 68
#define VSTR 72
__global__ __launch_bounds__(128) void flash_tf32(
    const float* __restrict__ Q, const float* __restrict__ K,
    const float* __restrict__ V, float* __restrict__ C)
{
    extern __shared__ uint32_t sm[];
    uint32_t* Qs = sm;                       // 64*68
    uint32_t* Ks = Qs + 64 * QSTR;           // 64*68
    uint32_t* Vs = Ks + 64 * QSTR;           // 64*72
    uint32_t* Ps = Vs + 64 * VSTR;           // 64*68

    const int tid = threadIdx.x;
    const int lane = tid & 31, wid = tid >> 5;
    const int g = lane >> 2, t = lane & 3;
    const int w16 = wid * 16;
    const int qt = blockIdx.x, h = blockIdx.y, b = blockIdx.z;

    const size_t head_off = (((size_t)b * H_SZ + h) * S_SZ) * DK_SZ;
    const float* Qb = Q + head_off + (size_t)qt * 64 * DK_SZ;
    const float* Kb = K + head_off;
    const float* Vb = V + head_off;

    // Load Q tile as tf32
#pragma unroll
    for (int rep = 0; rep < 8; rep++) {
        int idx = rep * 128 + tid;
        int r = idx >> 4, c4 = (idx & 15) << 2;
        float4 q4 = *(const float4*)&Qb[r * DK_SZ + c4];
        uint4 u = {f2t(q4.x), f2t(q4.y), f2t(q4.z), f2t(q4.w)};
        *(uint4*)&Qs[r * QSTR + c4] = u;
    }

    float o[8][4] = {};
    float mp0 = -1e30f, mp1 = -1e30f, l0 = 0.f, l1 = 0.f;

    for (int kt = 0; kt < S_SZ / 64; kt++) {
        // Load K/V tiles as tf32
#pragma unroll
        for (int rep = 0; rep < 8; rep++) {
            int idx = rep * 128 + tid;
            int r = idx >> 4, c4 = (idx & 15) << 2;
            float4 k4 = *(const float4*)&Kb[(kt * 64 + r) * DK_SZ + c4];
            uint4 uk = {f2t(k4.x), f2t(k4.y), f2t(k4.z), f2t(k4.w)};
            *(uint4*)&Ks[r * QSTR + c4] = uk;
            float4 v4 = *(const float4*)&Vb[(kt * 64 + r) * DK_SZ + c4];
            uint4 uv = {f2t(v4.x), f2t(v4.y), f2t(v4.z), f2t(v4.w)};
            *(uint4*)&Vs[r * VSTR + c4] = uv;
        }
        __syncthreads();

        // S = Q @ K^T  (warp rows w16..w16+15, all 64 key cols)
        float s[8][4] = {};
#pragma unroll
        for (int d8 = 0; d8 < 8; d8++) {
            uint32_t aq[4];
            aq[0] = Qs[(w16 + g) * QSTR + d8 * 8 + t];
            aq[1] = Qs[(w16 + g + 8) * QSTR + d8 * 8 + t];
            aq[2] = Qs[(w16 + g) * QSTR + d8 * 8 + t + 4];
            aq[3] = Qs[(w16 + g + 8) * QSTR + d8 * 8 + t + 4];
#pragma unroll
            for (int nt = 0; nt < 8; nt++) {
                uint32_t bk[2];
                bk[0] = Ks[(nt * 8 + g) * QSTR + d8 * 8 + t];
                bk[1] = Ks[(nt * 8 + g) * QSTR + d8 * 8 + t + 4];
                mma_tf32(s[nt], aq, bk);
            }
        }

        // Online softmax (rows r0 = g, r1 = g+8 within warp tile)
        float ml0 = -1e30f, ml1 = -1e30f;
#pragma unroll
        for (int nt = 0; nt < 8; nt++) {
            ml0 = fmaxf(ml0, fmaxf(s[nt][0], s[nt][1]));
            ml1 = fmaxf(ml1, fmaxf(s[nt][2], s[nt][3]));
        }
        ml0 = fmaxf(ml0, __shfl_xor_sync(0xffffffffu, ml0, 1));
        ml0 = fmaxf(ml0, __shfl_xor_sync(0xffffffffu, ml0, 2));
        ml1 = fmaxf(ml1, __shfl_xor_sync(0xffffffffu, ml1, 1));
        ml1 = fmaxf(ml1, __shfl_xor_sync(0xffffffffu, ml1, 2));
        float mn0 = fmaxf(mp0, ml0), mn1 = fmaxf(mp1, ml1);
        float a0 = __expf(mp0 - mn0), a1 = __expf(mp1 - mn1);
        mp0 = mn0;
        mp1 = mn1;
        float rs0 = 0.f, rs1 = 0.f;
#pragma unroll
        for (int nt = 0; nt < 8; nt++) {
            s[nt][0] = __expf(s[nt][0] - mn0);
            s[nt][1] = __expf(s[nt][1] - mn0);
            s[nt][2] = __expf(s[nt][2] - mn1);
            s[nt][3] = __expf(s[nt][3] - mn1);
            rs0 += s[nt][0] + s[nt][1];
            rs1 += s[nt][2] + s[nt][3];
        }
        rs0 += __shfl_xor_sync(0xffffffffu, rs0, 1);
        rs0 += __shfl_xor_sync(0xffffffffu, rs0, 2);
        rs1 += __shfl_xor_sync(0xffffffffu, rs1, 1);
        rs1 += __shfl_xor_sync(0xffffffffu, rs1, 2);
        l0 = l0 * a0 + rs0;
        l1 = l1 * a1 + rs1;

        // Rescale O, stage P (tf32) into per-warp smem rows
#pragma unroll
        for (int nt = 0; nt < 8; nt++) {
            o[nt][0] *= a0; o[nt][1] *= a0;
            o[nt][2] *= a1; o[nt][3] *= a1;
            uint2 p0 = {f2t(s[nt][0]), f2t(s[nt][1])};
            *(uint2*)&Ps[(w16 + g) * QSTR + nt * 8 + 2 * t] = p0;
            uint2 p1 = {f2t(s[nt][2]), f2t(s[nt][3])};
            *(uint2*)&Ps[(w16 + g + 8) * QSTR + nt * 8 + 2 * t] = p1;
        }
        __syncwarp();

        // O += P @ V
#pragma unroll
        for (int k8 = 0; k8 < 8; k8++) {
            uint32_t ap[4];
            ap[0] = Ps[(w16 + g) * QSTR + k8 * 8 + t];
            ap[1] = Ps[(w16 + g + 8) * QSTR + k8 * 8 + t];
            ap[2] = Ps[(w16 + g) * QSTR + k8 * 8 + t + 4];
            ap[3] = Ps[(w16 + g + 8) * QSTR + k8 * 8 + t + 4];
#pragma unroll
            for (int nt = 0; nt < 8; nt++) {
                uint32_t bv[2];
                bv[0] = Vs[(k8 * 8 + t) * VSTR + nt * 8 + g];
                bv[1] = Vs[(k8 * 8 + t + 4) * VSTR + nt * 8 + g];
                mma_tf32(o[nt], ap, bv);
            }
        }
        __syncthreads();   // protect K/V before next tile load
    }

    // Write context rows (normalize by l)
    float i0 = 1.0f / l0, i1 = 1.0f / l1;
    int srow0 = qt * 64 + w16 + g;
#pragma unroll
    for (int nt = 0; nt < 8; nt++) {
        int col = h * DK_SZ + nt * 8 + 2 * t;
        float* c0 = &C[((size_t)b * S_SZ + srow0) * D_SZ + col];
        c0[0] = o[nt][0] * i0;
        c0[1] = o[nt][1] * i0;
        float* c1 = &C[((size_t)b * S_SZ + srow0 + 8) * D_SZ + col];
        c1[0] = o[nt][2] * i1;
        c1[1] = o[nt][3] * i1;
    }
}

// ---------------------------------------------------------------------------
// Launch. Inputs: query, key, value, Wq, bq, Wk, bk, Wv, bv, Wo, bo
// ---------------------------------------------------------------------------
extern "C" void kernel_launch(void* const* d_in, const int* in_sizes, int n_in,
                              void* d_out, int out_size)
{
    const float* q  = (const float*)d_in[0];
    const float* k  = (const float*)d_in[1];
    const float* v  = (const float*)d_in[2];
    const float* Wq = (const float*)d_in[3];
    const float* bq = (const float*)d_in[4];
    const float* Wk = (const float*)d_in[5];
    const float* bk = (const float*)d_in[6];
    const float* Wv = (const float*)d_in[7];
    const float* bv = (const float*)d_in[8];
    const float* Wo = (const float*)d_in[9];
    const float* bo = (const float*)d_in[10];
    float* out = (float*)d_out;

    float *gq, *gk, *gv, *gc;
    cudaGetSymbolAddress((void**)&gq, g_Q);
    cudaGetSymbolAddress((void**)&gk, g_K);
    cudaGetSymbolAddress((void**)&gv, g_V);
    cudaGetSymbolAddress((void**)&gc, g_C);

    const int SMEM_ATTN = (64 * QSTR * 3 + 64 * VSTR) * 4;  // 70656 B
    cudaFuncSetAttribute(flash_tf32,
                         cudaFuncAttributeMaxDynamicSharedMemorySize, SMEM_ATTN);

    dim3 gemm_grid(D_SZ / 128, M_SZ / 128);  // (8, 32)
    const float qscale = 0.125f;              // 1/sqrt(64)

    gemm_tf32<<<gemm_grid, 256>>>(q, Wq, bq, gq, qscale, 1);
    gemm_tf32<<<gemm_grid, 256>>>(k, Wk, bk, gk, 1.0f, 1);
    gemm_tf32<<<gemm_grid, 256>>>(v, Wv, bv, gv, 1.0f, 1);

    dim3 attn_grid(S_SZ / 64, H_SZ, B_SZ);   // (32, 16, 2)
    flash_tf32<<<attn_grid, 128, SMEM_ATTN>>>(gq, gk, gv, gc);

    gemm_tf32<<<gemm_grid, 256>>>(gc, Wo, bo, out, 1.0f, 0);
}

// round 3
// speedup vs baseline: 3.8561x; 1.1799x over previous
#include <cuda_runtime.h>
#include <cstdint>

#define B_SZ 2
#define S_SZ 2048
#define D_SZ 1024
#define H_SZ 16
#define DK 64
#define M_SZ (B_SZ * S_SZ)

// Scratch (device globals; no runtime allocation allowed)
__device__ float g_Ar[3][4194304];   // tf32-rounded query,key,value
__device__ float g_Wr[4][1048576];   // tf32-rounded Wq,Wk,Wv,Wo
__device__ float g_Qh[4194304];      // Q in [B,H,S,dk], pre-scaled+rounded
__device__ float g_Kh[4194304];
__device__ float g_Vh[4194304];
__device__ float g_C[4194304];       // attention output, rounded

// ---------------------------------------------------------------------------
// helpers
// ---------------------------------------------------------------------------
__device__ __forceinline__ uint32_t f2t(float x) {
    uint32_t u;
    asm("cvt.rna.tf32.f32 %0, %1;" : "=r"(u) : "f"(x));
    return u;
}

__device__ __forceinline__ void mma_tf32(float c[4], const uint32_t a[4],
                                         const uint32_t b[2]) {
    asm volatile(
        "mma.sync.aligned.m16n8k8.row.col.f32.tf32.tf32.f32 "
        "{%0,%1,%2,%3}, {%4,%5,%6,%7}, {%8,%9}, {%0,%1,%2,%3};\n"
        : "+f"(c[0]), "+f"(c[1]), "+f"(c[2]), "+f"(c[3])
        : "r"(a[0]), "r"(a[1]), "r"(a[2]), "r"(a[3]), "r"(b[0]), "r"(b[1]));
}

__device__ __forceinline__ void cp16(uint32_t dst, const float* src) {
    asm volatile("cp.async.cg.shared.global [%0], [%1], 16;\n"
                 :: "r"(dst), "l"(src));
}
__device__ __forceinline__ void cp_commit() {
    asm volatile("cp.async.commit_group;\n");
}
template <int N> __device__ __forceinline__ void cp_wait() {
    asm volatile("cp.async.wait_group %0;\n" :: "n"(N));
}

// ---------------------------------------------------------------------------
// Prep: round all GEMM inputs to tf32 once. grid = (4096, 7), 256 thr.
// arrays 0-2: activations (1048576 float4); 3-6: weights (262144 float4)
// ---------------------------------------------------------------------------
__global__ void round_all_kernel(
    const float* __restrict__ q, const float* __restrict__ k,
    const float* __restrict__ v, const float* __restrict__ w0,
    const float* __restrict__ w1, const float* __restrict__ w2,
    const float* __restrict__ w3)
{
    const int a = blockIdx.y;
    const float* src;
    float* dst;
    int n4;
    switch (a) {
        case 0: src = q;  dst = g_Ar[0]; n4 = 1048576; break;
        case 1: src = k;  dst = g_Ar[1]; n4 = 1048576; break;
        case 2: src = v;  dst = g_Ar[2]; n4 = 1048576; break;
        case 3: src = w0; dst = g_Wr[0]; n4 = 262144; break;
        case 4: src = w1; dst = g_Wr[1]; n4 = 262144; break;
        case 5: src = w2; dst = g_Wr[2]; n4 = 262144; break;
        default: src = w3; dst = g_Wr[3]; n4 = 262144; break;
    }
    int i = blockIdx.x * blockDim.x + threadIdx.x;
    if (i >= n4) return;
    float4 t4 = ((const float4*)src)[i];
    uint4 u = {f2t(t4.x), f2t(t4.y), f2t(t4.z), f2t(t4.w)};
    ((uint4*)dst)[i] = u;
}

// ---------------------------------------------------------------------------
// tf32 GEMM: out[m][n] = (sum_k A[m][k]*W[n][k] + bias[n]) * scale
// A,W pre-rounded tf32. CTA 128x128, 4 warps of 64x64, BK=32, cp.async
// double buffered. mode 1: head layout [B,H,S,dk] + round output to tf32.
// ---------------------------------------------------------------------------
#define GST 36
__global__ __launch_bounds__(128, 2) void gemm_tf32(
    const float* __restrict__ A, const float* __restrict__ W,
    const float* __restrict__ bias, float* __restrict__ out,
    float scale, int mode)
{
    extern __shared__ float smg[];
    float* As = smg;                       // [2][128*36]
    float* Bs = smg + 2 * 128 * GST;       // [2][128*36]
    uint32_t As_u = (uint32_t)__cvta_generic_to_shared(As);
    uint32_t Bs_u = (uint32_t)__cvta_generic_to_shared(Bs);

    const int tid = threadIdx.x, lane = tid & 31, wid = tid >> 5;
    const int g = lane >> 2, t = lane & 3;
    const int warpM = wid & 1, warpN = wid >> 1;
    const int m0 = blockIdx.y * 128, n0 = blockIdx.x * 128;

    float acc[4][8][4] = {};

    auto fill = [&](int buf, int kb) {
        const float* Ap = A + (size_t)m0 * D_SZ + kb;
        const float* Wp = W + (size_t)n0 * D_SZ + kb;
        uint32_t ad = As_u + buf * 128 * GST * 4;
        uint32_t bd = Bs_u + buf * 128 * GST * 4;
#pragma unroll
        for (int c = 0; c < 8; c++) {
            int ch = c * 128 + tid;           // 0..1023
            int r = ch >> 3, cw = (ch & 7) << 2;
            cp16(ad + (r * GST + cw) * 4, Ap + (size_t)r * D_SZ + cw);
            cp16(bd + (r * GST + cw) * 4, Wp + (size_t)r * D_SZ + cw);
        }
        cp_commit();
    };

    fill(0, 0);
    for (int kb = 0; kb < D_SZ; kb += 32) {
        const int buf = (kb >> 5) & 1;
        if (kb + 32 < D_SZ) { fill(buf ^ 1, kb + 32); cp_wait<1>(); }
        else cp_wait<0>();
        __syncthreads();
        const float* Ab = As + buf * 128 * GST;
        const float* Bb = Bs + buf * 128 * GST;
#pragma unroll
        for (int ks = 0; ks < 4; ks++) {
            uint32_t af[4][4], bf[8][2];
#pragma unroll
            for (int mt = 0; mt < 4; mt++) {
                int rb = warpM * 64 + mt * 16;
                af[mt][0] = __float_as_uint(Ab[(rb + g) * GST + ks * 8 + t]);
                af[mt][1] = __float_as_uint(Ab[(rb + g + 8) * GST + ks * 8 + t]);
                af[mt][2] = __float_as_uint(Ab[(rb + g) * GST + ks * 8 + t + 4]);
                af[mt][3] = __float_as_uint(Ab[(rb + g + 8) * GST + ks * 8 + t + 4]);
            }
#pragma unroll
            for (int nt = 0; nt < 8; nt++) {
                int nb = warpN * 64 + nt * 8 + g;
                bf[nt][0] = __float_as_uint(Bb[nb * GST + ks * 8 + t]);
                bf[nt][1] = __float_as_uint(Bb[nb * GST + ks * 8 + t + 4]);
            }
#pragma unroll
            for (int mt = 0; mt < 4; mt++)
#pragma unroll
                for (int nt = 0; nt < 8; nt++)
                    mma_tf32(acc[mt][nt], af[mt], bf[nt]);
        }
        __syncthreads();
    }

    // epilogue
#pragma unroll
    for (int mt = 0; mt < 4; mt++) {
#pragma unroll
        for (int nt = 0; nt < 8; nt++) {
            int col = n0 + warpN * 64 + nt * 8 + 2 * t;
            float b0 = bias[col], b1 = bias[col + 1];
#pragma unroll
            for (int h2 = 0; h2 < 2; h2++) {
                int m = m0 + warpM * 64 + mt * 16 + g + h2 * 8;
                float v0 = (acc[mt][nt][h2 * 2 + 0] + b0) * scale;
                float v1 = (acc[mt][nt][h2 * 2 + 1] + b1) * scale;
                if (mode) {
                    int bb = m >> 11, s = m & 2047, hh = col >> 6, dh = col & 63;
                    float* o = &out[(((size_t)(bb * H_SZ + hh)) * S_SZ + s) * DK + dh];
                    o[0] = __uint_as_float(f2t(v0));
                    o[1] = __uint_as_float(f2t(v1));
                } else {
                    out[(size_t)m * D_SZ + col] = v0;
                    out[(size_t)m * D_SZ + col + 1] = v1;
                }
            }
        }
    }
}

// ---------------------------------------------------------------------------
// Flash attention (tf32 mma). CTA = 128 queries (4 warps x 32 rows),
// 64-key tiles double-buffered via cp.async. Q fragments in registers.
// Softmax in exp2 domain (log2e folded into Q scale).
// smem: [2] x (K 64x68 + V 64x72) = 17920 f, then Ps 128x68 = 8704 f.
// ---------------------------------------------------------------------------
#define KST 68
#define VST 72
#define PST 68
__global__ __launch_bounds__(128, 2) void flash_tf32(
    const float* __restrict__ Q, const float* __restrict__ K,
    const float* __restrict__ V, float* __restrict__ C)
{
    extern __shared__ float smf[];
    float* Ps = smf + 17920;
    uint32_t sm_u = (uint32_t)__cvta_generic_to_shared(smf);

    const int tid = threadIdx.x, lane = tid & 31, wid = tid >> 5;
    const int g = lane >> 2, t = lane & 3;
    const int w32 = wid * 32;
    const int qt = blockIdx.x, h = blockIdx.y, b = blockIdx.z;

    const size_t hoff = ((size_t)(b * H_SZ + h)) * S_SZ * DK;
    const float* Qg = Q + hoff + (size_t)qt * 128 * DK;
    const float* Kg = K + hoff;
    const float* Vg = V + hoff;

    // Stage Q (128x64) into buffer area, then pull fragments to registers
#pragma unroll
    for (int c = 0; c < 16; c++) {
        int ch = c * 128 + tid;               // 0..2047
        int r = ch >> 4, cw = (ch & 15) << 2;
        cp16(sm_u + (r * KST + cw) * 4, Qg + (size_t)r * DK + cw);
    }
    cp_commit();
    cp_wait<0>();
    __syncthreads();

    uint32_t qf[2][8][4];
#pragma unroll
    for (int blk = 0; blk < 2; blk++)
#pragma unroll
        for (int d8 = 0; d8 < 8; d8++) {
            int r0 = w32 + blk * 16 + g;
            qf[blk][d8][0] = __float_as_uint(smf[r0 * KST + d8 * 8 + t]);
            qf[blk][d8][1] = __float_as_uint(smf[(r0 + 8) * KST + d8 * 8 + t]);
            qf[blk][d8][2] = __float_as_uint(smf[r0 * KST + d8 * 8 + t + 4]);
            qf[blk][d8][3] = __float_as_uint(smf[(r0 + 8) * KST + d8 * 8 + t + 4]);
        }
    __syncthreads();

    auto fillKV = [&](int buf, int kt) {
        const float* Kp = Kg + (size_t)kt * 64 * DK;
        const float* Vp = Vg + (size_t)kt * 64 * DK;
        uint32_t kd = sm_u + buf * 8960 * 4;
        uint32_t vd = kd + 64 * KST * 4;
#pragma unroll
        for (int c = 0; c < 8; c++) {
            int ch = c * 128 + tid;           // 0..1023
            int r = ch >> 4, cw = (ch & 15) << 2;
            cp16(kd + (r * KST + cw) * 4, Kp + (size_t)r * DK + cw);
            cp16(vd + (r * VST + cw) * 4, Vp + (size_t)r * DK + cw);
        }
        cp_commit();
    };

    float o[2][8][4] = {};
    float mrun[2][2] = {{-1e30f, -1e30f}, {-1e30f, -1e30f}};
    float lrun[2][2] = {{0.f, 0.f}, {0.f, 0.f}};

    fillKV(0, 0);
    for (int kt = 0; kt < S_SZ / 64; kt++) {
        const int buf = kt & 1;
        if (kt + 1 < S_SZ / 64) { fillKV(buf ^ 1, kt + 1); cp_wait<1>(); }
        else cp_wait<0>();
        __syncthreads();

        const float* Ksb = smf + buf * 8960;
        const float* Vsb = Ksb + 64 * KST;

        // S = Q K^T for both row blocks (K fragments shared)
        float s[2][8][4] = {};
#pragma unroll
        for (int d8 = 0; d8 < 8; d8++) {
            uint32_t bk[8][2];
#pragma unroll
            for (int nt = 0; nt < 8; nt++) {
                bk[nt][0] = __float_as_uint(Ksb[(nt * 8 + g) * KST + d8 * 8 + t]);
                bk[nt][1] = __float_as_uint(Ksb[(nt * 8 + g) * KST + d8 * 8 + t + 4]);
            }
#pragma unroll
            for (int blk = 0; blk < 2; blk++)
#pragma unroll
                for (int nt = 0; nt < 8; nt++)
                    mma_tf32(s[blk][nt], qf[blk][d8], bk[nt]);
        }

        // online softmax per row block (rows g and g+8)
#pragma unroll
        for (int blk = 0; blk < 2; blk++) {
            float ml0 = -1e30f, ml1 = -1e30f;
#pragma unroll
            for (int nt = 0; nt < 8; nt++) {
                ml0 = fmaxf(ml0, fmaxf(s[blk][nt][0], s[blk][nt][1]));
                ml1 = fmaxf(ml1, fmaxf(s[blk][nt][2], s[blk][nt][3]));
            }
            ml0 = fmaxf(ml0, __shfl_xor_sync(~0u, ml0, 1));
            ml0 = fmaxf(ml0, __shfl_xor_sync(~0u, ml0, 2));
            ml1 = fmaxf(ml1, __shfl_xor_sync(~0u, ml1, 1));
            ml1 = fmaxf(ml1, __shfl_xor_sync(~0u, ml1, 2));
            float mn0 = fmaxf(mrun[blk][0], ml0), mn1 = fmaxf(mrun[blk][1], ml1);
            float a0 = exp2f(mrun[blk][0] - mn0), a1 = exp2f(mrun[blk][1] - mn1);
            mrun[blk][0] = mn0;
            mrun[blk][1] = mn1;
            float rs0 = 0.f, rs1 = 0.f;
#pragma unroll
            for (int nt = 0; nt < 8; nt++) {
                s[blk][nt][0] = exp2f(s[blk][nt][0] - mn0);
                s[blk][nt][1] = exp2f(s[blk][nt][1] - mn0);
                s[blk][nt][2] = exp2f(s[blk][nt][2] - mn1);
                s[blk][nt][3] = exp2f(s[blk][nt][3] - mn1);
                rs0 += s[blk][nt][0] + s[blk][nt][1];
                rs1 += s[blk][nt][2] + s[blk][nt][3];
            }
            rs0 += __shfl_xor_sync(~0u, rs0, 1);
            rs0 += __shfl_xor_sync(~0u, rs0, 2);
            rs1 += __shfl_xor_sync(~0u, rs1, 1);
            rs1 += __shfl_xor_sync(~0u, rs1, 2);
            lrun[blk][0] = lrun[blk][0] * a0 + rs0;
            lrun[blk][1] = lrun[blk][1] * a1 + rs1;
            int r0 = w32 + blk * 16 + g;
#pragma unroll
            for (int nt = 0; nt < 8; nt++) {
                o[blk][nt][0] *= a0; o[blk][nt][1] *= a0;
                o[blk][nt][2] *= a1; o[blk][nt][3] *= a1;
                *(float2*)&Ps[r0 * PST + nt * 8 + 2 * t] =
                    make_float2(s[blk][nt][0], s[blk][nt][1]);
                *(float2*)&Ps[(r0 + 8) * PST + nt * 8 + 2 * t] =
                    make_float2(s[blk][nt][2], s[blk][nt][3]);
            }
        }
        __syncwarp();

        // O += P V (V fragments shared across both row blocks)
#pragma unroll
        for (int k8 = 0; k8 < 8; k8++) {
            uint32_t ap0[4], ap1[4];
            int r0 = w32 + g, r1 = w32 + 16 + g;
            ap0[0] = __float_as_uint(Ps[r0 * PST + k8 * 8 + t]);
            ap0[1] = __float_as_uint(Ps[(r0 + 8) * PST + k8 * 8 + t]);
            ap0[2] = __float_as_uint(Ps[r0 * PST + k8 * 8 + t + 4]);
            ap0[3] = __float_as_uint(Ps[(r0 + 8) * PST + k8 * 8 + t + 4]);
            ap1[0] = __float_as_uint(Ps[r1 * PST + k8 * 8 + t]);
            ap1[1] = __float_as_uint(Ps[(r1 + 8) * PST + k8 * 8 + t]);
            ap1[2] = __float_as_uint(Ps[r1 * PST + k8 * 8 + t + 4]);
            ap1[3] = __float_as_uint(Ps[(r1 + 8) * PST + k8 * 8 + t + 4]);
#pragma unroll
            for (int nt = 0; nt < 8; nt++) {
                uint32_t bv[2];
                bv[0] = __float_as_uint(Vsb[(k8 * 8 + t) * VST + nt * 8 + g]);
                bv[1] = __float_as_uint(Vsb[(k8 * 8 + t + 4) * VST + nt * 8 + g]);
                mma_tf32(o[0][nt], ap0, bv);
                mma_tf32(o[1][nt], ap1, bv);
            }
        }
        __syncthreads();
    }

    // epilogue: normalize + round (feeds O-projection)
#pragma unroll
    for (int blk = 0; blk < 2; blk++) {
        float i0 = 1.f / lrun[blk][0], i1 = 1.f / lrun[blk][1];
        int srow = qt * 128 + w32 + blk * 16 + g;
#pragma unroll
        for (int nt = 0; nt < 8; nt++) {
            int col = h * DK + nt * 8 + 2 * t;
            float* c0 = &C[((size_t)b * S_SZ + srow) * D_SZ + col];
            c0[0] = __uint_as_float(f2t(o[blk][nt][0] * i0));
            c0[1] = __uint_as_float(f2t(o[blk][nt][1] * i0));
            float* c1 = &C[((size_t)b * S_SZ + srow + 8) * D_SZ + col];
            c1[0] = __uint_as_float(f2t(o[blk][nt][2] * i1));
            c1[1] = __uint_as_float(f2t(o[blk][nt][3] * i1));
        }
    }
}

// ---------------------------------------------------------------------------
// Launch. Inputs: query, key, value, Wq, bq, Wk, bk, Wv, bv, Wo, bo
// ---------------------------------------------------------------------------
extern "C" void kernel_launch(void* const* d_in, const int* in_sizes, int n_in,
                              void* d_out, int out_size)
{
    const float* q  = (const float*)d_in[0];
    const float* k  = (const float*)d_in[1];
    const float* v  = (const float*)d_in[2];
    const float* Wq = (const float*)d_in[3];
    const float* bq = (const float*)d_in[4];
    const float* Wk = (const float*)d_in[5];
    const float* bk = (const float*)d_in[6];
    const float* Wv = (const float*)d_in[7];
    const float* bv = (const float*)d_in[8];
    const float* Wo = (const float*)d_in[9];
    const float* bo = (const float*)d_in[10];
    float* out = (float*)d_out;

    float *ar, *wr, *gq, *gk, *gv, *gc;
    cudaGetSymbolAddress((void**)&ar, g_Ar);
    cudaGetSymbolAddress((void**)&wr, g_Wr);
    cudaGetSymbolAddress((void**)&gq, g_Qh);
    cudaGetSymbolAddress((void**)&gk, g_Kh);
    cudaGetSymbolAddress((void**)&gv, g_Vh);
    cudaGetSymbolAddress((void**)&gc, g_C);
    float* ar0 = ar;
    float* ar1 = ar + 4194304;
    float* ar2 = ar + 2 * 4194304;
    float* wr0 = wr;
    float* wr1 = wr + 1048576;
    float* wr2 = wr + 2 * 1048576;
    float* wr3 = wr + 3 * 1048576;

    const int SMEM_GEMM = 2 * 2 * 128 * GST * 4;               // 73728
    const int SMEM_ATTN = (2 * 8960 + 128 * PST) * 4;          // 106496
    cudaFuncSetAttribute(gemm_tf32,
                         cudaFuncAttributeMaxDynamicSharedMemorySize, SMEM_GEMM);
    cudaFuncSetAttribute(flash_tf32,
                         cudaFuncAttributeMaxDynamicSharedMemorySize, SMEM_ATTN);

    round_all_kernel<<<dim3(4096, 7), 256>>>(q, k, v, Wq, Wk, Wv, Wo);

    dim3 ggrid(D_SZ / 128, M_SZ / 128);   // (8, 32)
    const float qscale = 0.125f * 1.4426950408889634f;  // 1/sqrt(dk) * log2(e)

    gemm_tf32<<<ggrid, 128, SMEM_GEMM>>>(ar0, wr0, bq, gq, qscale, 1);
    gemm_tf32<<<ggrid, 128, SMEM_GEMM>>>(ar1, wr1, bk, gk, 1.0f, 1);
    gemm_tf32<<<ggrid, 128, SMEM_GEMM>>>(ar2, wr2, bv, gv, 1.0f, 1);

    dim3 agrid(S_SZ / 128, H_SZ, B_SZ);   // (16, 16, 2)
    flash_tf32<<<agrid, 128, SMEM_ATTN>>>(gq, gk, gv, gc);

    gemm_tf32<<<ggrid, 128, SMEM_GEMM>>>(gc, wr3, bo, out, 1.0f, 0);
}

// round 5
// speedup vs baseline: 7.6607x; 1.9866x over previous
#include <cuda_runtime.h>
#include <cuda_fp16.h>
#include <cstdint>

#define B_SZ 2
#define S_SZ 2048
#define D_SZ 1024
#define H_SZ 16
#define DK 64
#define M_SZ (B_SZ * S_SZ)

// Scratch (device globals; no runtime allocation allowed)
__device__ __half g_Ah[3][4194304];  // fp16 query,key,value
__device__ __half g_Wh[4][1048576];  // fp16 Wq,Wk,Wv,Wo
__device__ __half g_Qh[4194304];     // Q [B,H,S,dk], pre-scaled, fp16
__device__ __half g_Kh[4194304];
__device__ __half g_Vh[4194304];
__device__ __half g_Ch[4194304];     // attention output [B,S,D], fp16

// ---------------------------------------------------------------------------
// helpers
// ---------------------------------------------------------------------------
__device__ __forceinline__ uint32_t pack_h2(float lo, float hi) {
    uint32_t d;
    asm("cvt.rn.f16x2.f32 %0, %1, %2;" : "=r"(d) : "f"(hi), "f"(lo));
    return d;
}

__device__ __forceinline__ void mma_f16(float c[4], const uint32_t a[4],
                                        const uint32_t b[2]) {
    asm volatile(
        "mma.sync.aligned.m16n8k16.row.col.f32.f16.f16.f32 "
        "{%0,%1,%2,%3}, {%4,%5,%6,%7}, {%8,%9}, {%0,%1,%2,%3};\n"
        : "+f"(c[0]), "+f"(c[1]), "+f"(c[2]), "+f"(c[3])
        : "r"(a[0]), "r"(a[1]), "r"(a[2]), "r"(a[3]), "r"(b[0]), "r"(b[1]));
}

__device__ __forceinline__ void ldsm4(uint32_t r[4], uint32_t addr) {
    asm volatile(
        "ldmatrix.sync.aligned.m8n8.x4.shared.b16 {%0,%1,%2,%3}, [%4];"
        : "=r"(r[0]), "=r"(r[1]), "=r"(r[2]), "=r"(r[3]) : "r"(addr));
}
__device__ __forceinline__ void ldsm4t(uint32_t r[4], uint32_t addr) {
    asm volatile(
        "ldmatrix.sync.aligned.m8n8.x4.trans.shared.b16 {%0,%1,%2,%3}, [%4];"
        : "=r"(r[0]), "=r"(r[1]), "=r"(r[2]), "=r"(r[3]) : "r"(addr));
}

__device__ __forceinline__ void cp16(uint32_t dst, const void* src) {
    asm volatile("cp.async.cg.shared.global [%0], [%1], 16;\n"
                 :: "r"(dst), "l"(src));
}
__device__ __forceinline__ void cp_commit() {
    asm volatile("cp.async.commit_group;\n");
}
template <int N> __device__ __forceinline__ void cp_wait() {
    asm volatile("cp.async.wait_group %0;\n" :: "n"(N));
}

#define SW128(off) ((off) ^ (((off) >> 3) & 0x70))

// ---------------------------------------------------------------------------
// Prep: convert all GEMM inputs to fp16 once.
// grid (4096, 7), 256 thr. y 0-2: activations (1048576 float4), 3-6: weights.
// ---------------------------------------------------------------------------
__global__ void prep_half(
    const float* __restrict__ q, const float* __restrict__ k,
    const float* __restrict__ v, const float* __restrict__ w0,
    const float* __restrict__ w1, const float* __restrict__ w2,
    const float* __restrict__ w3)
{
    const int a = blockIdx.y;
    const float* src;
    __half* dst;
    int n4;
    switch (a) {
        case 0: src = q;  dst = g_Ah[0]; n4 = 1048576; break;
        case 1: src = k;  dst = g_Ah[1]; n4 = 1048576; break;
        case 2: src = v;  dst = g_Ah[2]; n4 = 1048576; break;
        case 3: src = w0; dst = g_Wh[0]; n4 = 262144; break;
        case 4: src = w1; dst = g_Wh[1]; n4 = 262144; break;
        case 5: src = w2; dst = g_Wh[2]; n4 = 262144; break;
        default: src = w3; dst = g_Wh[3]; n4 = 262144; break;
    }
    int i = blockIdx.x * blockDim.x + threadIdx.x;
    if (i >= n4) return;
    float4 t4 = ((const float4*)src)[i];
    uint2 u = {pack_h2(t4.x, t4.y), pack_h2(t4.z, t4.w)};
    ((uint2*)dst)[i] = u;
}

// ---------------------------------------------------------------------------
// fp16 GEMM: out[m][n] = (sum_k A[m][k]*W[n][k] + bias[n]) * scale
// A [4096,1024] half, W [1024,1024] half (torch Linear: row n = output).
// CTA 128x128, BK=64 (128B rows, SW128), 8 warps (2m x 4n), warp 64x32.
// cp.async double-buffered. mode 1: half out in [B,H,S,dk]; mode 0: f32 flat.
// smem: 2 x (A 16KB + B 16KB) = 64KB.
// ---------------------------------------------------------------------------
__global__ __launch_bounds__(256, 2) void gemm_h(
    const __half* __restrict__ A, const __half* __restrict__ W,
    const float* __restrict__ bias, __half* __restrict__ outh,
    float* __restrict__ outf, float scale, int mode)
{
    extern __shared__ char smraw[];
    uint32_t smb = (uint32_t)__cvta_generic_to_shared(smraw);

    const int tid = threadIdx.x, lane = tid & 31, wid = tid >> 5;
    const int g = lane >> 2, t = lane & 3;
    const int warpM = wid & 1, warpN = wid >> 1;
    const int m0 = blockIdx.y * 128, n0 = blockIdx.x * 128;

    float acc[4][4][4] = {};

    // ldmatrix lane address components (within-tile)
    const int a_row = (lane & 7) + ((lane >> 3) & 1) * 8;   // A/B row in 16-block
    const int a_kb = ((lane >> 4) & 1) * 16;                // A k-byte offset
    const int b_row = (lane & 7) + ((lane >> 4) & 1) * 8;   // B n row in 16-block
    const int b_kb = ((lane >> 3) & 1) * 16;                // B k-byte offset

    auto fill = [&](int buf, int kt) {
        uint32_t ab = smb + buf * 32768;
        uint32_t bb = ab + 16384;
        const __half* As = A + (size_t)m0 * D_SZ + kt * 64;
        const __half* Ws = W + (size_t)n0 * D_SZ + kt * 64;
#pragma unroll
        for (int i = 0; i < 4; i++) {
            int ch = i * 256 + tid;          // 0..1023
            int r = ch >> 3;                 // 0..127
            int cb = (ch & 7) * 16;          // 0..112
            uint32_t sw = SW128(r * 128 + cb);
            cp16(ab + sw, (const char*)(As + (size_t)r * D_SZ) + cb);
            cp16(bb + sw, (const char*)(Ws + (size_t)r * D_SZ) + cb);
        }
        cp_commit();
    };

    fill(0, 0);
    for (int kb = 0; kb < 16; kb++) {
        const int buf = kb & 1;
        if (kb + 1 < 16) { fill(buf ^ 1, kb + 1); cp_wait<1>(); }
        else cp_wait<0>();
        __syncthreads();

        uint32_t ab = smb + buf * 32768;
        uint32_t bb = ab + 16384;
#pragma unroll
        for (int ks = 0; ks < 4; ks++) {
            uint32_t af[4][4], bf[4][2];
#pragma unroll
            for (int mt = 0; mt < 4; mt++) {
                int row = warpM * 64 + mt * 16 + a_row;
                ldsm4(af[mt], ab + SW128(row * 128 + ks * 32 + a_kb));
            }
#pragma unroll
            for (int nb = 0; nb < 2; nb++) {
                uint32_t r4[4];
                int row = warpN * 32 + nb * 16 + b_row;
                ldsm4(r4, bb + SW128(row * 128 + ks * 32 + b_kb));
                bf[nb * 2][0] = r4[0]; bf[nb * 2][1] = r4[1];
                bf[nb * 2 + 1][0] = r4[2]; bf[nb * 2 + 1][1] = r4[3];
            }
#pragma unroll
            for (int mt = 0; mt < 4; mt++)
#pragma unroll
                for (int nt = 0; nt < 4; nt++)
                    mma_f16(acc[mt][nt], af[mt], bf[nt]);
        }
        __syncthreads();
    }

    // epilogue
#pragma unroll
    for (int mt = 0; mt < 4; mt++) {
#pragma unroll
        for (int nt = 0; nt < 4; nt++) {
            int col = n0 + warpN * 32 + nt * 8 + 2 * t;
            float b0 = bias[col], b1 = bias[col + 1];
            int r0 = m0 + warpM * 64 + mt * 16 + g;
            float v00 = (acc[mt][nt][0] + b0) * scale;
            float v01 = (acc[mt][nt][1] + b1) * scale;
            float v10 = (acc[mt][nt][2] + b0) * scale;
            float v11 = (acc[mt][nt][3] + b1) * scale;
            if (mode) {
                int hh = col >> 6, dh = col & 63;
                int bb0 = r0 >> 11, s0 = r0 & 2047;
                __half* p0 = &outh[(((size_t)(bb0 * H_SZ + hh)) * S_SZ + s0) * DK + dh];
                *(uint32_t*)p0 = pack_h2(v00, v01);
                int r1 = r0 + 8;
                int bb1 = r1 >> 11, s1 = r1 & 2047;
                __half* p1 = &outh[(((size_t)(bb1 * H_SZ + hh)) * S_SZ + s1) * DK + dh];
                *(uint32_t*)p1 = pack_h2(v10, v11);
            } else {
                *(float2*)&outf[(size_t)r0 * D_SZ + col] = make_float2(v00, v01);
                *(float2*)&outf[(size_t)(r0 + 8) * D_SZ + col] = make_float2(v10, v11);
            }
        }
    }
}

// ---------------------------------------------------------------------------
// Flash attention, fp16 mma. CTA = 128 queries, 8 warps x 16 rows.
// 64-key tiles double-buffered. Q and P fragments live in registers
// (P uses the C->A fragment layout identity). V via ldmatrix.trans.
// smem: Q 16KB + 2 x (K 8KB + V 8KB) = 48KB. Softmax in exp2 domain.
// ---------------------------------------------------------------------------
__global__ __launch_bounds__(256, 2) void flash_h(
    const __half* __restrict__ Q, const __half* __restrict__ K,
    const __half* __restrict__ V, __half* __restrict__ C)
{
    extern __shared__ char smraw[];
    uint32_t smb = (uint32_t)__cvta_generic_to_shared(smraw);
    const uint32_t Qb_s = smb;                 // 128 rows x 128B
    // K/V buffers at smb + 16384 + buf*16384 (K 8KB then V 8KB)

    const int tid = threadIdx.x, lane = tid & 31, wid = tid >> 5;
    const int g = lane >> 2, t = lane & 3;
    const int w16 = wid * 16;
    const int qt = blockIdx.x, h = blockIdx.y, b = blockIdx.z;

    const size_t hoff = ((size_t)(b * H_SZ + h)) * S_SZ * DK;
    const __half* Qg = Q + hoff + (size_t)qt * 128 * DK;
    const __half* Kg = K + hoff;
    const __half* Vg = V + hoff;

    // ldmatrix lane address components
    const int a_row = (lane & 7) + ((lane >> 3) & 1) * 8;
    const int a_kb = ((lane >> 4) & 1) * 16;
    const int b_row = (lane & 7) + ((lane >> 4) & 1) * 8;
    const int b_kb = ((lane >> 3) & 1) * 16;

    // Stage Q (128 x 64 halves = 128B rows)
#pragma unroll
    for (int i = 0; i < 4; i++) {
        int ch = i * 256 + tid;
        int r = ch >> 3, cb = (ch & 7) * 16;
        cp16(Qb_s + SW128(r * 128 + cb), (const char*)(Qg + (size_t)r * DK) + cb);
    }
    cp_commit();

    auto fillKV = [&](int buf, int kt) {
        uint32_t kd = smb + 16384 + buf * 16384;
        uint32_t vd = kd + 8192;
        const __half* Kp = Kg + (size_t)kt * 64 * DK;
        const __half* Vp = Vg + (size_t)kt * 64 * DK;
#pragma unroll
        for (int i = 0; i < 2; i++) {
            int ch = i * 256 + tid;           // 0..511
            int r = ch >> 3, cb = (ch & 7) * 16;
            uint32_t sw = SW128(r * 128 + cb);
            cp16(kd + sw, (const char*)(Kp + (size_t)r * DK) + cb);
            cp16(vd + sw, (const char*)(Vp + (size_t)r * DK) + cb);
        }
        cp_commit();
    };

    fillKV(0, 0);
    cp_wait<1>();   // Q done
    __syncthreads();

    // Q fragments in registers: 4 k16 chunks
    uint32_t qf[4][4];
#pragma unroll
    for (int ks = 0; ks < 4; ks++) {
        int row = w16 + a_row;
        ldsm4(qf[ks], Qb_s + SW128(row * 128 + ks * 32 + a_kb));
    }

    float o[8][4] = {};
    float m0r = -1e30f, m1r = -1e30f, l0 = 0.f, l1 = 0.f;

    for (int kt = 0; kt < S_SZ / 64; kt++) {
        const int buf = kt & 1;
        if (kt + 1 < S_SZ / 64) { fillKV(buf ^ 1, kt + 1); cp_wait<1>(); }
        else cp_wait<0>();
        __syncthreads();

        uint32_t Ks = smb + 16384 + buf * 16384;
        uint32_t Vs = Ks + 8192;

        // S = Q K^T : 8 nt tiles (64 keys), 4 k16 chunks
        float s[8][4] = {};
#pragma unroll
        for (int ks = 0; ks < 4; ks++) {
#pragma unroll
            for (int nb = 0; nb < 4; nb++) {
                uint32_t r4[4];
                int row = nb * 16 + b_row;
                ldsm4(r4, Ks + SW128(row * 128 + ks * 32 + b_kb));
                uint32_t b0[2] = {r4[0], r4[1]};
                uint32_t b1[2] = {r4[2], r4[3]};
                mma_f16(s[nb * 2], qf[ks], b0);
                mma_f16(s[nb * 2 + 1], qf[ks], b1);
            }
        }

        // online softmax (rows g, g+8)
        float ml0 = -1e30f, ml1 = -1e30f;
#pragma unroll
        for (int nt = 0; nt < 8; nt++) {
            ml0 = fmaxf(ml0, fmaxf(s[nt][0], s[nt][1]));
            ml1 = fmaxf(ml1, fmaxf(s[nt][2], s[nt][3]));
        }
        ml0 = fmaxf(ml0, __shfl_xor_sync(~0u, ml0, 1));
        ml0 = fmaxf(ml0, __shfl_xor_sync(~0u, ml0, 2));
        ml1 = fmaxf(ml1, __shfl_xor_sync(~0u, ml1, 1));
        ml1 = fmaxf(ml1, __shfl_xor_sync(~0u, ml1, 2));
        float mn0 = fmaxf(m0r, ml0), mn1 = fmaxf(m1r, ml1);
        float a0 = exp2f(m0r - mn0), a1 = exp2f(m1r - mn1);
        m0r = mn0;
        m1r = mn1;
        float rs0 = 0.f, rs1 = 0.f;
        uint32_t ph[8][2];
#pragma unroll
        for (int nt = 0; nt < 8; nt++) {
            float p0 = exp2f(s[nt][0] - mn0);
            float p1 = exp2f(s[nt][1] - mn0);
            float p2 = exp2f(s[nt][2] - mn1);
            float p3 = exp2f(s[nt][3] - mn1);
            rs0 += p0 + p1;
            rs1 += p2 + p3;
            ph[nt][0] = pack_h2(p0, p1);   // A-frag regs a0 (row g)
            ph[nt][1] = pack_h2(p2, p3);   // a1 (row g+8)
        }
        rs0 += __shfl_xor_sync(~0u, rs0, 1);
        rs0 += __shfl_xor_sync(~0u, rs0, 2);
        rs1 += __shfl_xor_sync(~0u, rs1, 1);
        rs1 += __shfl_xor_sync(~0u, rs1, 2);
        l0 = l0 * a0 + rs0;
        l1 = l1 * a1 + rs1;
#pragma unroll
        for (int nt = 0; nt < 8; nt++) {
            o[nt][0] *= a0; o[nt][1] *= a0;
            o[nt][2] *= a1; o[nt][3] *= a1;
        }

        // O += P V : 4 k16 chunks, V via ldmatrix.trans
#pragma unroll
        for (int kc = 0; kc < 4; kc++) {
            uint32_t ap[4] = {ph[kc * 2][0], ph[kc * 2][1],
                              ph[kc * 2 + 1][0], ph[kc * 2 + 1][1]};
#pragma unroll
            for (int nb = 0; nb < 4; nb++) {
                uint32_t r4[4];
                int krow = kc * 16 + a_row;          // V rows (key idx)
                int nbyte = nb * 32 + a_kb;          // dk col bytes
                ldsm4t(r4, Vs + SW128(krow * 128 + nbyte));
                uint32_t b0[2] = {r4[0], r4[1]};
                uint32_t b1[2] = {r4[2], r4[3]};
                mma_f16(o[nb * 2], ap, b0);
                mma_f16(o[nb * 2 + 1], ap, b1);
            }
        }
        __syncthreads();
    }

    // epilogue: normalize, write fp16 context [B,S,D]
    float i0 = 1.f / l0, i1 = 1.f / l1;
    int srow = qt * 128 + w16 + g;
#pragma unroll
    for (int nt = 0; nt < 8; nt++) {
        int col = h * DK + nt * 8 + 2 * t;
        __half* c0 = &C[((size_t)b * S_SZ + srow) * D_SZ + col];
        *(uint32_t*)c0 = pack_h2(o[nt][0] * i0, o[nt][1] * i0);
        __half* c1 = &C[((size_t)b * S_SZ + srow + 8) * D_SZ + col];
        *(uint32_t*)c1 = pack_h2(o[nt][2] * i1, o[nt][3] * i1);
    }
}

// ---------------------------------------------------------------------------
// Launch. Inputs: query, key, value, Wq, bq, Wk, bk, Wv, bv, Wo, bo
// ---------------------------------------------------------------------------
extern "C" void kernel_launch(void* const* d_in, const int* in_sizes, int n_in,
                              void* d_out, int out_size)
{
    const float* q  = (const float*)d_in[0];
    const float* k  = (const float*)d_in[1];
    const float* v  = (const float*)d_in[2];
    const float* Wq = (const float*)d_in[3];
    const float* bq = (const float*)d_in[4];
    const float* Wk = (const float*)d_in[5];
    const float* bk = (const float*)d_in[6];
    const float* Wv = (const float*)d_in[7];
    const float* bv = (const float*)d_in[8];
    const float* Wo = (const float*)d_in[9];
    const float* bo = (const float*)d_in[10];
    float* out = (float*)d_out;

    __half *ah, *wh, *gq, *gk, *gv, *gc;
    cudaGetSymbolAddress((void**)&ah, g_Ah);
    cudaGetSymbolAddress((void**)&wh, g_Wh);
    cudaGetSymbolAddress((void**)&gq, g_Qh);
    cudaGetSymbolAddress((void**)&gk, g_Kh);
    cudaGetSymbolAddress((void**)&gv, g_Vh);
    cudaGetSymbolAddress((void**)&gc, g_Ch);
    __half* ah0 = ah;
    __half* ah1 = ah + 4194304;
    __half* ah2 = ah + 2 * 4194304;
    __half* wh0 = wh;
    __half* wh1 = wh + 1048576;
    __half* wh2 = wh + 2 * 1048576;
    __half* wh3 = wh + 3 * 1048576;

    const int SMEM_GEMM = 65536;
    const int SMEM_ATTN = 49152;
    cudaFuncSetAttribute(gemm_h,
                         cudaFuncAttributeMaxDynamicSharedMemorySize, SMEM_GEMM);
    cudaFuncSetAttribute(flash_h,
                         cudaFuncAttributeMaxDynamicSharedMemorySize, SMEM_ATTN);

    prep_half<<<dim3(4096, 7), 256>>>(q, k, v, Wq, Wk, Wv, Wo);

    dim3 ggrid(D_SZ / 128, M_SZ / 128);   // (8, 32)
    const float qscale = 0.125f * 1.4426950408889634f;  // 1/sqrt(dk) * log2(e)

    gemm_h<<<ggrid, 256, SMEM_GEMM>>>(ah0, wh0, bq, gq, nullptr, qscale, 1);
    gemm_h<<<ggrid, 256, SMEM_GEMM>>>(ah1, wh1, bk, gk, nullptr, 1.0f, 1);
    gemm_h<<<ggrid, 256, SMEM_GEMM>>>(ah2, wh2, bv, gv, nullptr, 1.0f, 1);

    dim3 agrid(S_SZ / 128, H_SZ, B_SZ);   // (16, 16, 2)
    flash_h<<<agrid, 256, SMEM_ATTN>>>(gq, gk, gv, gc);

    gemm_h<<<ggrid, 256, SMEM_GEMM>>>(gc, wh3, bo, nullptr, out, 1.0f, 0);
}

// round 6
// speedup vs baseline: 7.9114x; 1.0327x over previous
#include <cuda_runtime.h>
#include <cuda_fp16.h>
#include <cstdint>

#define B_SZ 2
#define S_SZ 2048
#define D_SZ 1024
#define H_SZ 16
#define DK 64
#define M_SZ (B_SZ * S_SZ)

// Scratch (device globals; no runtime allocation allowed)
__device__ __half g_Ah[3][4194304];  // fp16 query,key,value
__device__ __half g_Wh[4][1048576];  // fp16 Wq,Wk,Wv,Wo
__device__ __half g_QKV[3][4194304]; // Q/K/V [B,H,S,dk] fp16 (Q pre-scaled)
__device__ __half g_Ch[4194304];     // attention output [B,S,D], fp16

// ---------------------------------------------------------------------------
// helpers
// ---------------------------------------------------------------------------
__device__ __forceinline__ uint32_t pack_h2(float lo, float hi) {
    uint32_t d;
    asm("cvt.rn.f16x2.f32 %0, %1, %2;" : "=r"(d) : "f"(hi), "f"(lo));
    return d;
}

__device__ __forceinline__ void mma_f16(float c[4], const uint32_t a[4],
                                        const uint32_t b[2]) {
    asm volatile(
        "mma.sync.aligned.m16n8k16.row.col.f32.f16.f16.f32 "
        "{%0,%1,%2,%3}, {%4,%5,%6,%7}, {%8,%9}, {%0,%1,%2,%3};\n"
        : "+f"(c[0]), "+f"(c[1]), "+f"(c[2]), "+f"(c[3])
        : "r"(a[0]), "r"(a[1]), "r"(a[2]), "r"(a[3]), "r"(b[0]), "r"(b[1]));
}

__device__ __forceinline__ void ldsm4(uint32_t r[4], uint32_t addr) {
    asm volatile(
        "ldmatrix.sync.aligned.m8n8.x4.shared.b16 {%0,%1,%2,%3}, [%4];"
        : "=r"(r[0]), "=r"(r[1]), "=r"(r[2]), "=r"(r[3]) : "r"(addr));
}
__device__ __forceinline__ void ldsm4t(uint32_t r[4], uint32_t addr) {
    asm volatile(
        "ldmatrix.sync.aligned.m8n8.x4.trans.shared.b16 {%0,%1,%2,%3}, [%4];"
        : "=r"(r[0]), "=r"(r[1]), "=r"(r[2]), "=r"(r[3]) : "r"(addr));
}

__device__ __forceinline__ void cp16(uint32_t dst, const void* src) {
    asm volatile("cp.async.cg.shared.global [%0], [%1], 16;\n"
                 :: "r"(dst), "l"(src));
}
__device__ __forceinline__ void cp_commit() {
    asm volatile("cp.async.commit_group;\n");
}
template <int N> __device__ __forceinline__ void cp_wait() {
    asm volatile("cp.async.wait_group %0;\n" :: "n"(N));
}

#define SW128(off) ((off) ^ (((off) >> 3) & 0x70))

// ---------------------------------------------------------------------------
// Prep: convert all GEMM inputs to fp16 once.
// ---------------------------------------------------------------------------
__global__ void prep_half(
    const float* __restrict__ q, const float* __restrict__ k,
    const float* __restrict__ v, const float* __restrict__ w0,
    const float* __restrict__ w1, const float* __restrict__ w2,
    const float* __restrict__ w3)
{
    const int a = blockIdx.y;
    const float* src;
    __half* dst;
    int n4;
    switch (a) {
        case 0: src = q;  dst = g_Ah[0]; n4 = 1048576; break;
        case 1: src = k;  dst = g_Ah[1]; n4 = 1048576; break;
        case 2: src = v;  dst = g_Ah[2]; n4 = 1048576; break;
        case 3: src = w0; dst = g_Wh[0]; n4 = 262144; break;
        case 4: src = w1; dst = g_Wh[1]; n4 = 262144; break;
        case 5: src = w2; dst = g_Wh[2]; n4 = 262144; break;
        default: src = w3; dst = g_Wh[3]; n4 = 262144; break;
    }
    int i = blockIdx.x * blockDim.x + threadIdx.x;
    if (i >= n4) return;
    float4 t4 = ((const float4*)src)[i];
    uint2 u = {pack_h2(t4.x, t4.y), pack_h2(t4.z, t4.w)};
    ((uint2*)dst)[i] = u;
}

// ---------------------------------------------------------------------------
// GEMM core: out[m][n] = (sum_k A[m][k]*W[n][k] + bias[n]) * scale
// CTA 128x128, BK=64 (SW128 rows), 8 warps (2m x 4n), warp 64x32.
// 3-stage cp.async pipeline, ONE __syncthreads per k-iteration.
// smem: 3 x (A 16KB + B 16KB) = 96KB.
// ---------------------------------------------------------------------------
__device__ __forceinline__ void gemm_core(
    const __half* __restrict__ A, const __half* __restrict__ W,
    const float* __restrict__ bias, __half* __restrict__ outh,
    float* __restrict__ outf, float scale, int mode, char* smraw)
{
    uint32_t smb = (uint32_t)__cvta_generic_to_shared(smraw);

    const int tid = threadIdx.x, lane = tid & 31, wid = tid >> 5;
    const int g = lane >> 2, t = lane & 3;
    const int warpM = wid & 1, warpN = wid >> 1;
    const int m0 = blockIdx.y * 128, n0 = blockIdx.x * 128;

    float acc[4][4][4] = {};

    const int a_row = (lane & 7) + ((lane >> 3) & 1) * 8;
    const int a_kb = ((lane >> 4) & 1) * 16;
    const int b_row = (lane & 7) + ((lane >> 4) & 1) * 8;
    const int b_kb = ((lane >> 3) & 1) * 16;

    auto fill = [&](int buf, int kt) {
        uint32_t ab = smb + buf * 32768;
        uint32_t bb = ab + 16384;
        const __half* As = A + (size_t)m0 * D_SZ + kt * 64;
        const __half* Ws = W + (size_t)n0 * D_SZ + kt * 64;
#pragma unroll
        for (int i = 0; i < 4; i++) {
            int ch = i * 256 + tid;
            int r = ch >> 3;
            int cb = (ch & 7) * 16;
            uint32_t sw = SW128(r * 128 + cb);
            cp16(ab + sw, (const char*)(As + (size_t)r * D_SZ) + cb);
            cp16(bb + sw, (const char*)(Ws + (size_t)r * D_SZ) + cb);
        }
        cp_commit();
    };

    fill(0, 0);
    fill(1, 1);
    int buf = 0, fbuf = 2;
    for (int kb = 0; kb < 16; kb++) {
        if (kb == 15) cp_wait<0>(); else cp_wait<1>();
        __syncthreads();
        if (kb + 2 < 16) {
            fill(fbuf, kb + 2);
            fbuf = (fbuf == 2) ? 0 : fbuf + 1;
        }
        uint32_t ab = smb + buf * 32768;
        uint32_t bb = ab + 16384;
#pragma unroll
        for (int ks = 0; ks < 4; ks++) {
            uint32_t af[4][4], bf[4][2];
#pragma unroll
            for (int mt = 0; mt < 4; mt++) {
                int row = warpM * 64 + mt * 16 + a_row;
                ldsm4(af[mt], ab + SW128(row * 128 + ks * 32 + a_kb));
            }
#pragma unroll
            for (int nb = 0; nb < 2; nb++) {
                uint32_t r4[4];
                int row = warpN * 32 + nb * 16 + b_row;
                ldsm4(r4, bb + SW128(row * 128 + ks * 32 + b_kb));
                bf[nb * 2][0] = r4[0]; bf[nb * 2][1] = r4[1];
                bf[nb * 2 + 1][0] = r4[2]; bf[nb * 2 + 1][1] = r4[3];
            }
#pragma unroll
            for (int mt = 0; mt < 4; mt++)
#pragma unroll
                for (int nt = 0; nt < 4; nt++)
                    mma_f16(acc[mt][nt], af[mt], bf[nt]);
        }
        buf = (buf == 2) ? 0 : buf + 1;
    }

    // epilogue
#pragma unroll
    for (int mt = 0; mt < 4; mt++) {
#pragma unroll
        for (int nt = 0; nt < 4; nt++) {
            int col = n0 + warpN * 32 + nt * 8 + 2 * t;
            float b0 = bias[col], b1 = bias[col + 1];
            int r0 = m0 + warpM * 64 + mt * 16 + g;
            float v00 = (acc[mt][nt][0] + b0) * scale;
            float v01 = (acc[mt][nt][1] + b1) * scale;
            float v10 = (acc[mt][nt][2] + b0) * scale;
            float v11 = (acc[mt][nt][3] + b1) * scale;
            if (mode) {
                int hh = col >> 6, dh = col & 63;
                int bb0 = r0 >> 11, s0 = r0 & 2047;
                __half* p0 = &outh[(((size_t)(bb0 * H_SZ + hh)) * S_SZ + s0) * DK + dh];
                *(uint32_t*)p0 = pack_h2(v00, v01);
                int r1 = r0 + 8;
                int bb1 = r1 >> 11, s1 = r1 & 2047;
                __half* p1 = &outh[(((size_t)(bb1 * H_SZ + hh)) * S_SZ + s1) * DK + dh];
                *(uint32_t*)p1 = pack_h2(v10, v11);
            } else {
                *(float2*)&outf[(size_t)r0 * D_SZ + col] = make_float2(v00, v01);
                *(float2*)&outf[(size_t)(r0 + 8) * D_SZ + col] = make_float2(v10, v11);
            }
        }
    }
}

// Fused Q/K/V projections: blockIdx.z selects input/weight/output set.
__global__ __launch_bounds__(256, 2) void gemm_qkv(
    const float* __restrict__ bq, const float* __restrict__ bk,
    const float* __restrict__ bv)
{
    extern __shared__ char smraw[];
    const int z = blockIdx.z;
    const float* bias = (z == 0) ? bq : (z == 1) ? bk : bv;
    const float scale = (z == 0) ? 0.125f * 1.4426950408889634f : 1.0f;
    gemm_core(g_Ah[z], g_Wh[z], bias, g_QKV[z], nullptr, scale, 1, smraw);
}

// Output projection: fp16 context @ Wo^T + bo -> f32 out
__global__ __launch_bounds__(256, 2) void gemm_o(
    const float* __restrict__ bo, float* __restrict__ out)
{
    extern __shared__ char smraw[];
    gemm_core(g_Ch, g_Wh[3], bo, nullptr, out, 1.0f, 0, smraw);
}

// ---------------------------------------------------------------------------
// Flash attention, fp16 mma. CTA = 128 queries, 8 warps x 16 rows.
// 64-key tiles, 3-stage cp.async KV pipeline, ONE sync per iteration.
// Q and P fragments in registers; V via ldmatrix.trans.
// smem: Q 16KB + 3 x (K 8KB + V 8KB) = 64KB. Softmax in exp2 domain.
// ---------------------------------------------------------------------------
__global__ __launch_bounds__(256, 2) void flash_h(
    const __half* __restrict__ Q, const __half* __restrict__ K,
    const __half* __restrict__ V, __half* __restrict__ C)
{
    extern __shared__ char smraw[];
    uint32_t smb = (uint32_t)__cvta_generic_to_shared(smraw);
    const uint32_t Qb_s = smb;

    const int tid = threadIdx.x, lane = tid & 31, wid = tid >> 5;
    const int g = lane >> 2, t = lane & 3;
    const int w16 = wid * 16;
    const int qt = blockIdx.x, h = blockIdx.y, b = blockIdx.z;

    const size_t hoff = ((size_t)(b * H_SZ + h)) * S_SZ * DK;
    const __half* Qg = Q + hoff + (size_t)qt * 128 * DK;
    const __half* Kg = K + hoff;
    const __half* Vg = V + hoff;

    const int a_row = (lane & 7) + ((lane >> 3) & 1) * 8;
    const int a_kb = ((lane >> 4) & 1) * 16;
    const int b_row = (lane & 7) + ((lane >> 4) & 1) * 8;
    const int b_kb = ((lane >> 3) & 1) * 16;

    // Stage Q (group 0)
#pragma unroll
    for (int i = 0; i < 4; i++) {
        int ch = i * 256 + tid;
        int r = ch >> 3, cb = (ch & 7) * 16;
        cp16(Qb_s + SW128(r * 128 + cb), (const char*)(Qg + (size_t)r * DK) + cb);
    }
    cp_commit();

    auto fillKV = [&](int buf, int kt) {
        uint32_t kd = smb + 16384 + buf * 16384;
        uint32_t vd = kd + 8192;
        const __half* Kp = Kg + (size_t)kt * 64 * DK;
        const __half* Vp = Vg + (size_t)kt * 64 * DK;
#pragma unroll
        for (int i = 0; i < 2; i++) {
            int ch = i * 256 + tid;
            int r = ch >> 3, cb = (ch & 7) * 16;
            uint32_t sw = SW128(r * 128 + cb);
            cp16(kd + sw, (const char*)(Kp + (size_t)r * DK) + cb);
            cp16(vd + sw, (const char*)(Vp + (size_t)r * DK) + cb);
        }
        cp_commit();
    };

    fillKV(0, 0);
    fillKV(1, 1);
    cp_wait<2>();   // Q landed
    __syncthreads();

    uint32_t qf[4][4];
#pragma unroll
    for (int ks = 0; ks < 4; ks++) {
        int row = w16 + a_row;
        ldsm4(qf[ks], Qb_s + SW128(row * 128 + ks * 32 + a_kb));
    }

    float o[8][4] = {};
    float m0r = -1e30f, m1r = -1e30f, l0 = 0.f, l1 = 0.f;

    int buf = 0, fbuf = 2;
    const int NT = S_SZ / 64;  // 32
    for (int kt = 0; kt < NT; kt++) {
        if (kt == NT - 1) cp_wait<0>(); else cp_wait<1>();
        __syncthreads();
        if (kt + 2 < NT) {
            fillKV(fbuf, kt + 2);
            fbuf = (fbuf == 2) ? 0 : fbuf + 1;
        }

        uint32_t Ks = smb + 16384 + buf * 16384;
        uint32_t Vs = Ks + 8192;
        buf = (buf == 2) ? 0 : buf + 1;

        // S = Q K^T
        float s[8][4] = {};
#pragma unroll
        for (int ks = 0; ks < 4; ks++) {
#pragma unroll
            for (int nb = 0; nb < 4; nb++) {
                uint32_t r4[4];
                int row = nb * 16 + b_row;
                ldsm4(r4, Ks + SW128(row * 128 + ks * 32 + b_kb));
                uint32_t b0[2] = {r4[0], r4[1]};
                uint32_t b1[2] = {r4[2], r4[3]};
                mma_f16(s[nb * 2], qf[ks], b0);
                mma_f16(s[nb * 2 + 1], qf[ks], b1);
            }
        }

        // online softmax (rows g, g+8)
        float ml0 = -1e30f, ml1 = -1e30f;
#pragma unroll
        for (int nt = 0; nt < 8; nt++) {
            ml0 = fmaxf(ml0, fmaxf(s[nt][0], s[nt][1]));
            ml1 = fmaxf(ml1, fmaxf(s[nt][2], s[nt][3]));
        }
        ml0 = fmaxf(ml0, __shfl_xor_sync(~0u, ml0, 1));
        ml0 = fmaxf(ml0, __shfl_xor_sync(~0u, ml0, 2));
        ml1 = fmaxf(ml1, __shfl_xor_sync(~0u, ml1, 1));
        ml1 = fmaxf(ml1, __shfl_xor_sync(~0u, ml1, 2));
        float mn0 = fmaxf(m0r, ml0), mn1 = fmaxf(m1r, ml1);
        float a0 = exp2f(m0r - mn0), a1 = exp2f(m1r - mn1);
        m0r = mn0;
        m1r = mn1;
        float rs0 = 0.f, rs1 = 0.f;
        uint32_t ph[8][2];
#pragma unroll
        for (int nt = 0; nt < 8; nt++) {
            float p0 = exp2f(s[nt][0] - mn0);
            float p1 = exp2f(s[nt][1] - mn0);
            float p2 = exp2f(s[nt][2] - mn1);
            float p3 = exp2f(s[nt][3] - mn1);
            rs0 += p0 + p1;
            rs1 += p2 + p3;
            ph[nt][0] = pack_h2(p0, p1);
            ph[nt][1] = pack_h2(p2, p3);
        }
        rs0 += __shfl_xor_sync(~0u, rs0, 1);
        rs0 += __shfl_xor_sync(~0u, rs0, 2);
        rs1 += __shfl_xor_sync(~0u, rs1, 1);
        rs1 += __shfl_xor_sync(~0u, rs1, 2);
        l0 = l0 * a0 + rs0;
        l1 = l1 * a1 + rs1;
#pragma unroll
        for (int nt = 0; nt < 8; nt++) {
            o[nt][0] *= a0; o[nt][1] *= a0;
            o[nt][2] *= a1; o[nt][3] *= a1;
        }

        // O += P V
#pragma unroll
        for (int kc = 0; kc < 4; kc++) {
            uint32_t ap[4] = {ph[kc * 2][0], ph[kc * 2][1],
                              ph[kc * 2 + 1][0], ph[kc * 2 + 1][1]};
#pragma unroll
            for (int nb = 0; nb < 4; nb++) {
                uint32_t r4[4];
                int krow = kc * 16 + a_row;
                int nbyte = nb * 32 + a_kb;
                ldsm4t(r4, Vs + SW128(krow * 128 + nbyte));
                uint32_t b0[2] = {r4[0], r4[1]};
                uint32_t b1[2] = {r4[2], r4[3]};
                mma_f16(o[nb * 2], ap, b0);
                mma_f16(o[nb * 2 + 1], ap, b1);
            }
        }
    }

    // epilogue: normalize, write fp16 context [B,S,D]
    float i0 = 1.f / l0, i1 = 1.f / l1;
    int srow = qt * 128 + w16 + g;
#pragma unroll
    for (int nt = 0; nt < 8; nt++) {
        int col = h * DK + nt * 8 + 2 * t;
        __half* c0 = &C[((size_t)b * S_SZ + srow) * D_SZ + col];
        *(uint32_t*)c0 = pack_h2(o[nt][0] * i0, o[nt][1] * i0);
        __half* c1 = &C[((size_t)b * S_SZ + srow + 8) * D_SZ + col];
        *(uint32_t*)c1 = pack_h2(o[nt][2] * i1, o[nt][3] * i1);
    }
}

// ---------------------------------------------------------------------------
// Launch. Inputs: query, key, value, Wq, bq, Wk, bk, Wv, bv, Wo, bo
// ---------------------------------------------------------------------------
extern "C" void kernel_launch(void* const* d_in, const int* in_sizes, int n_in,
                              void* d_out, int out_size)
{
    const float* q  = (const float*)d_in[0];
    const float* k  = (const float*)d_in[1];
    const float* v  = (const float*)d_in[2];
    const float* Wq = (const float*)d_in[3];
    const float* bq = (const float*)d_in[4];
    const float* Wk = (const float*)d_in[5];
    const float* bk = (const float*)d_in[6];
    const float* Wv = (const float*)d_in[7];
    const float* bv = (const float*)d_in[8];
    const float* Wo = (const float*)d_in[9];
    const float* bo = (const float*)d_in[10];
    float* out = (float*)d_out;

    __half *gqkv, *gc;
    cudaGetSymbolAddress((void**)&gqkv, g_QKV);
    cudaGetSymbolAddress((void**)&gc, g_Ch);
    __half* gq = gqkv;
    __half* gk = gqkv + 4194304;
    __half* gv = gqkv + 2 * 4194304;

    const int SMEM_GEMM = 98304;   // 3 x 32KB
    const int SMEM_ATTN = 65536;   // Q 16KB + 3 x 16KB
    cudaFuncSetAttribute(gemm_qkv,
                         cudaFuncAttributeMaxDynamicSharedMemorySize, SMEM_GEMM);
    cudaFuncSetAttribute(gemm_o,
                         cudaFuncAttributeMaxDynamicSharedMemorySize, SMEM_GEMM);
    cudaFuncSetAttribute(flash_h,
                         cudaFuncAttributeMaxDynamicSharedMemorySize, SMEM_ATTN);

    prep_half<<<dim3(4096, 7), 256>>>(q, k, v, Wq, Wk, Wv, Wo);

    dim3 gqkv_grid(D_SZ / 128, M_SZ / 128, 3);  // (8, 32, 3)
    gemm_qkv<<<gqkv_grid, 256, SMEM_GEMM>>>(bq, bk, bv);

    dim3 agrid(S_SZ / 128, H_SZ, B_SZ);         // (16, 16, 2)
    flash_h<<<agrid, 256, SMEM_ATTN>>>(gq, gk, gv, gc);

    dim3 go_grid(D_SZ / 128, M_SZ / 128);       // (8, 32)
    gemm_o<<<go_grid, 256, SMEM_GEMM>>>(bo, out);
}

// round 8
// speedup vs baseline: 8.4655x; 1.0700x over previous
#include <cuda_runtime.h>
#include <cuda_fp16.h>
#include <cstdint>

#define B_SZ 2
#define S_SZ 2048
#define D_SZ 1024
#define H_SZ 16
#define DK 64
#define M_SZ (B_SZ * S_SZ)

// Scratch (device globals; no runtime allocation allowed)
__device__ __half g_Ah[3][4194304];  // fp16 query,key,value
__device__ __half g_Wh[4][1048576];  // fp16 Wq,Wk,Wv,Wo
__device__ __half g_QKV[3][4194304]; // Q/K/V [B,H,S,dk] fp16 (Q pre-scaled)
__device__ __half g_Ch[4194304];     // attention output [B,S,D], fp16

// ---------------------------------------------------------------------------
// helpers
// ---------------------------------------------------------------------------
__device__ __forceinline__ uint32_t pack_h2(float lo, float hi) {
    uint32_t d;
    asm("cvt.rn.f16x2.f32 %0, %1, %2;" : "=r"(d) : "f"(hi), "f"(lo));
    return d;
}

__device__ __forceinline__ float ex2(float x) {
    float y;
    asm("ex2.approx.ftz.f32 %0, %1;" : "=f"(y) : "f"(x));
    return y;
}

__device__ __forceinline__ void mma_f16(float c[4], const uint32_t a[4],
                                        const uint32_t b[2]) {
    asm volatile(
        "mma.sync.aligned.m16n8k16.row.col.f32.f16.f16.f32 "
        "{%0,%1,%2,%3}, {%4,%5,%6,%7}, {%8,%9}, {%0,%1,%2,%3};\n"
        : "+f"(c[0]), "+f"(c[1]), "+f"(c[2]), "+f"(c[3])
        : "r"(a[0]), "r"(a[1]), "r"(a[2]), "r"(a[3]), "r"(b[0]), "r"(b[1]));
}

__device__ __forceinline__ void ldsm4(uint32_t r[4], uint32_t addr) {
    asm volatile(
        "ldmatrix.sync.aligned.m8n8.x4.shared.b16 {%0,%1,%2,%3}, [%4];"
        : "=r"(r[0]), "=r"(r[1]), "=r"(r[2]), "=r"(r[3]) : "r"(addr));
}
__device__ __forceinline__ void ldsm4t(uint32_t r[4], uint32_t addr) {
    asm volatile(
        "ldmatrix.sync.aligned.m8n8.x4.trans.shared.b16 {%0,%1,%2,%3}, [%4];"
        : "=r"(r[0]), "=r"(r[1]), "=r"(r[2]), "=r"(r[3]) : "r"(addr));
}

__device__ __forceinline__ void cp16(uint32_t dst, const void* src) {
    asm volatile("cp.async.cg.shared.global [%0], [%1], 16;\n"
                 :: "r"(dst), "l"(src));
}
__device__ __forceinline__ void cp_commit() {
    asm volatile("cp.async.commit_group;\n");
}
template <int N> __device__ __forceinline__ void cp_wait() {
    asm volatile("cp.async.wait_group %0;\n" :: "n"(N));
}

#define SW128(off) ((off) ^ (((off) >> 3) & 0x70))

// ---------------------------------------------------------------------------
// Prep: convert all GEMM inputs to fp16 once.
// ---------------------------------------------------------------------------
__global__ void prep_half(
    const float* __restrict__ q, const float* __restrict__ k,
    const float* __restrict__ v, const float* __restrict__ w0,
    const float* __restrict__ w1, const float* __restrict__ w2,
    const float* __restrict__ w3)
{
    const int a = blockIdx.y;
    const float* src;
    __half* dst;
    int n4;
    switch (a) {
        case 0: src = q;  dst = g_Ah[0]; n4 = 1048576; break;
        case 1: src = k;  dst = g_Ah[1]; n4 = 1048576; break;
        case 2: src = v;  dst = g_Ah[2]; n4 = 1048576; break;
        case 3: src = w0; dst = g_Wh[0]; n4 = 262144; break;
        case 4: src = w1; dst = g_Wh[1]; n4 = 262144; break;
        case 5: src = w2; dst = g_Wh[2]; n4 = 262144; break;
        default: src = w3; dst = g_Wh[3]; n4 = 262144; break;
    }
    int i = blockIdx.x * blockDim.x + threadIdx.x;
    if (i >= n4) return;
    float4 t4 = ((const float4*)src)[i];
    uint2 u = {pack_h2(t4.x, t4.y), pack_h2(t4.z, t4.w)};
    ((uint2*)dst)[i] = u;
}

// ---------------------------------------------------------------------------
// GEMM core: out[m][n] = (sum_k A[m][k]*W[n][k] + bias[n]) * scale
// CTA 128x128, 4 warps (2m x 2n), warp tile 64x64, BK=64 (SW128 rows).
// 3-stage cp.async pipeline. smem 3 x 32KB = 96KB. 128 threads.
// Each A/B datum read by only 2 warps -> smem traffic under crossbar BW.
// ---------------------------------------------------------------------------
__device__ __forceinline__ void gemm_core(
    const __half* __restrict__ A, const __half* __restrict__ W,
    const float* __restrict__ bias, __half* __restrict__ outh,
    float* __restrict__ outf, float scale, int mode, char* smraw)
{
    uint32_t smb = (uint32_t)__cvta_generic_to_shared(smraw);

    const int tid = threadIdx.x, lane = tid & 31, wid = tid >> 5;
    const int g = lane >> 2, t = lane & 3;
    const int warpM = wid & 1, warpN = wid >> 1;
    const int m0 = blockIdx.y * 128, n0 = blockIdx.x * 128;

    float acc[4][8][4] = {};

    const int a_row = (lane & 7) + ((lane >> 3) & 1) * 8;
    const int a_kb = ((lane >> 4) & 1) * 16;
    const int b_row = (lane & 7) + ((lane >> 4) & 1) * 8;
    const int b_kb = ((lane >> 3) & 1) * 16;

    auto fill = [&](int buf, int kt) {
        uint32_t ab = smb + buf * 32768;
        uint32_t bb = ab + 16384;
        const __half* As = A + (size_t)m0 * D_SZ + kt * 64;
        const __half* Ws = W + (size_t)n0 * D_SZ + kt * 64;
#pragma unroll
        for (int i = 0; i < 8; i++) {
            int ch = i * 128 + tid;          // 0..1023
            int r = ch >> 3;                 // 0..127
            int cb = (ch & 7) * 16;
            uint32_t sw = SW128(r * 128 + cb);
            cp16(ab + sw, (const char*)(As + (size_t)r * D_SZ) + cb);
            cp16(bb + sw, (const char*)(Ws + (size_t)r * D_SZ) + cb);
        }
        cp_commit();
    };

    fill(0, 0);
    fill(1, 1);
    int buf = 0, fbuf = 2;
    for (int kb = 0; kb < 16; kb++) {
        if (kb == 15) cp_wait<0>(); else cp_wait<1>();
        __syncthreads();
        if (kb + 2 < 16) {
            fill(fbuf, kb + 2);
            fbuf = (fbuf == 2) ? 0 : fbuf + 1;
        }
        uint32_t ab = smb + buf * 32768;
        uint32_t bb = ab + 16384;
#pragma unroll
        for (int ks = 0; ks < 4; ks++) {
            uint32_t af[4][4], bf[8][2];
#pragma unroll
            for (int mt = 0; mt < 4; mt++) {
                int row = warpM * 64 + mt * 16 + a_row;
                ldsm4(af[mt], ab + SW128(row * 128 + ks * 32 + a_kb));
            }
#pragma unroll
            for (int nb = 0; nb < 4; nb++) {
                uint32_t r4[4];
                int row = warpN * 64 + nb * 16 + b_row;
                ldsm4(r4, bb + SW128(row * 128 + ks * 32 + b_kb));
                bf[nb * 2][0] = r4[0]; bf[nb * 2][1] = r4[1];
                bf[nb * 2 + 1][0] = r4[2]; bf[nb * 2 + 1][1] = r4[3];
            }
#pragma unroll
            for (int mt = 0; mt < 4; mt++)
#pragma unroll
                for (int nt = 0; nt < 8; nt++)
                    mma_f16(acc[mt][nt], af[mt], bf[nt]);
        }
        buf = (buf == 2) ? 0 : buf + 1;
    }

    // epilogue
#pragma unroll
    for (int mt = 0; mt < 4; mt++) {
#pragma unroll
        for (int nt = 0; nt < 8; nt++) {
            int col = n0 + warpN * 64 + nt * 8 + 2 * t;
            float b0 = bias[col], b1 = bias[col + 1];
            int r0 = m0 + warpM * 64 + mt * 16 + g;
            float v00 = (acc[mt][nt][0] + b0) * scale;
            float v01 = (acc[mt][nt][1] + b1) * scale;
            float v10 = (acc[mt][nt][2] + b0) * scale;
            float v11 = (acc[mt][nt][3] + b1) * scale;
            if (mode) {
                int hh = col >> 6, dh = col & 63;
                int bb0 = r0 >> 11, s0 = r0 & 2047;
                __half* p0 = &outh[(((size_t)(bb0 * H_SZ + hh)) * S_SZ + s0) * DK + dh];
                *(uint32_t*)p0 = pack_h2(v00, v01);
                int r1 = r0 + 8;
                int bb1 = r1 >> 11, s1 = r1 & 2047;
                __half* p1 = &outh[(((size_t)(bb1 * H_SZ + hh)) * S_SZ + s1) * DK + dh];
                *(uint32_t*)p1 = pack_h2(v10, v11);
            } else {
                *(float2*)&outf[(size_t)r0 * D_SZ + col] = make_float2(v00, v01);
                *(float2*)&outf[(size_t)(r0 + 8) * D_SZ + col] = make_float2(v10, v11);
            }
        }
    }
}

// Fused Q/K/V projections: blockIdx.z selects input/weight/output set.
__global__ __launch_bounds__(128) void gemm_qkv(
    const float* __restrict__ bq, const float* __restrict__ bk,
    const float* __restrict__ bv)
{
    extern __shared__ char smraw[];
    const int z = blockIdx.z;
    const float* bias = (z == 0) ? bq : (z == 1) ? bk : bv;
    const float scale = (z == 0) ? 0.125f * 1.4426950408889634f : 1.0f;
    gemm_core(g_Ah[z], g_Wh[z], bias, g_QKV[z], nullptr, scale, 1, smraw);
}

// Output projection: fp16 context @ Wo^T + bo -> f32 out
__global__ __launch_bounds__(128) void gemm_o(
    const float* __restrict__ bo, float* __restrict__ out)
{
    extern __shared__ char smraw[];
    gemm_core(g_Ch, g_Wh[3], bo, nullptr, out, 1.0f, 0, smraw);
}

// ---------------------------------------------------------------------------
// Flash attention, fp16 mma. CTA = 128 queries, 4 warps x 32 rows
// (2 row-blocks of 16). K/V fragments shared across row-blocks.
// 64-key tiles, 3-stage cp.async pipeline.
// smem: Q 16KB + 3 x (K 8KB + V 8KB) = 64KB. Softmax in exp2 domain.
// ---------------------------------------------------------------------------
__global__ __launch_bounds__(128) void flash_h(
    const __half* __restrict__ Q, const __half* __restrict__ K,
    const __half* __restrict__ V, __half* __restrict__ C)
{
    extern __shared__ char smraw[];
    uint32_t smb = (uint32_t)__cvta_generic_to_shared(smraw);
    const uint32_t Qb_s = smb;

    const int tid = threadIdx.x, lane = tid & 31, wid = tid >> 5;
    const int g = lane >> 2, t = lane & 3;
    const int w32 = wid * 32;
    const int qt = blockIdx.x, h = blockIdx.y, b = blockIdx.z;

    const size_t hoff = ((size_t)(b * H_SZ + h)) * S_SZ * DK;
    const __half* Qg = Q + hoff + (size_t)qt * 128 * DK;
    const __half* Kg = K + hoff;
    const __half* Vg = V + hoff;

    const int a_row = (lane & 7) + ((lane >> 3) & 1) * 8;
    const int a_kb = ((lane >> 4) & 1) * 16;
    const int b_row = (lane & 7) + ((lane >> 4) & 1) * 8;
    const int b_kb = ((lane >> 3) & 1) * 16;

    // Stage Q (128 x 64 halves = 128B rows)
#pragma unroll
    for (int i = 0; i < 8; i++) {
        int ch = i * 128 + tid;
        int r = ch >> 3, cb = (ch & 7) * 16;
        cp16(Qb_s + SW128(r * 128 + cb), (const char*)(Qg + (size_t)r * DK) + cb);
    }
    cp_commit();

    auto fillKV = [&](int buf, int kt) {
        uint32_t kd = smb + 16384 + buf * 16384;
        uint32_t vd = kd + 8192;
        const __half* Kp = Kg + (size_t)kt * 64 * DK;
        const __half* Vp = Vg + (size_t)kt * 64 * DK;
#pragma unroll
        for (int i = 0; i < 4; i++) {
            int ch = i * 128 + tid;           // 0..511
            int r = ch >> 3, cb = (ch & 7) * 16;
            uint32_t sw = SW128(r * 128 + cb);
            cp16(kd + sw, (const char*)(Kp + (size_t)r * DK) + cb);
            cp16(vd + sw, (const char*)(Vp + (size_t)r * DK) + cb);
        }
        cp_commit();
    };

    fillKV(0, 0);
    fillKV(1, 1);
    cp_wait<2>();   // Q landed
    __syncthreads();

    // Q fragments: 2 row-blocks x 4 k16 chunks
    uint32_t qf[2][4][4];
#pragma unroll
    for (int blk = 0; blk < 2; blk++)
#pragma unroll
        for (int ks = 0; ks < 4; ks++) {
            int row = w32 + blk * 16 + a_row;
            ldsm4(qf[blk][ks], Qb_s + SW128(row * 128 + ks * 32 + a_kb));
        }

    float o[2][8][4] = {};
    float mr[2][2] = {{-1e30f, -1e30f}, {-1e30f, -1e30f}};
    float lr[2][2] = {{0.f, 0.f}, {0.f, 0.f}};

    int buf = 0, fbuf = 2;
    const int NT = S_SZ / 64;  // 32
    for (int kt = 0; kt < NT; kt++) {
        if (kt == NT - 1) cp_wait<0>(); else cp_wait<1>();
        __syncthreads();
        if (kt + 2 < NT) {
            fillKV(fbuf, kt + 2);
            fbuf = (fbuf == 2) ? 0 : fbuf + 1;
        }

        uint32_t Ks = smb + 16384 + buf * 16384;
        uint32_t Vs = Ks + 8192;
        buf = (buf == 2) ? 0 : buf + 1;

        // S = Q K^T : K fragments loaded once, used by both row-blocks
        float s[2][8][4] = {};
#pragma unroll
        for (int ks = 0; ks < 4; ks++) {
#pragma unroll
            for (int nb = 0; nb < 4; nb++) {
                uint32_t r4[4];
                int row = nb * 16 + b_row;
                ldsm4(r4, Ks + SW128(row * 128 + ks * 32 + b_kb));
                uint32_t b0[2] = {r4[0], r4[1]};
                uint32_t b1[2] = {r4[2], r4[3]};
#pragma unroll
                for (int blk = 0; blk < 2; blk++) {
                    mma_f16(s[blk][nb * 2], qf[blk][ks], b0);
                    mma_f16(s[blk][nb * 2 + 1], qf[blk][ks], b1);
                }
            }
        }

        // online softmax per block (rows g, g+8)
        uint32_t ph[2][8][2];
#pragma unroll
        for (int blk = 0; blk < 2; blk++) {
            float ml0 = -1e30f, ml1 = -1e30f;
#pragma unroll
            for (int nt = 0; nt < 8; nt++) {
                ml0 = fmaxf(ml0, fmaxf(s[blk][nt][0], s[blk][nt][1]));
                ml1 = fmaxf(ml1, fmaxf(s[blk][nt][2], s[blk][nt][3]));
            }
            ml0 = fmaxf(ml0, __shfl_xor_sync(~0u, ml0, 1));
            ml0 = fmaxf(ml0, __shfl_xor_sync(~0u, ml0, 2));
            ml1 = fmaxf(ml1, __shfl_xor_sync(~0u, ml1, 1));
            ml1 = fmaxf(ml1, __shfl_xor_sync(~0u, ml1, 2));
            float mn0 = fmaxf(mr[blk][0], ml0), mn1 = fmaxf(mr[blk][1], ml1);
            float a0 = ex2(mr[blk][0] - mn0), a1 = ex2(mr[blk][1] - mn1);
            mr[blk][0] = mn0;
            mr[blk][1] = mn1;
            float rs0 = 0.f, rs1 = 0.f;
#pragma unroll
            for (int nt = 0; nt < 8; nt++) {
                float p0 = ex2(s[blk][nt][0] - mn0);
                float p1 = ex2(s[blk][nt][1] - mn0);
                float p2 = ex2(s[blk][nt][2] - mn1);
                float p3 = ex2(s[blk][nt][3] - mn1);
                rs0 += p0 + p1;
                rs1 += p2 + p3;
                ph[blk][nt][0] = pack_h2(p0, p1);
                ph[blk][nt][1] = pack_h2(p2, p3);
            }
            rs0 += __shfl_xor_sync(~0u, rs0, 1);
            rs0 += __shfl_xor_sync(~0u, rs0, 2);
            rs1 += __shfl_xor_sync(~0u, rs1, 1);
            rs1 += __shfl_xor_sync(~0u, rs1, 2);
            lr[blk][0] = lr[blk][0] * a0 + rs0;
            lr[blk][1] = lr[blk][1] * a1 + rs1;
#pragma unroll
            for (int nt = 0; nt < 8; nt++) {
                o[blk][nt][0] *= a0; o[blk][nt][1] *= a0;
                o[blk][nt][2] *= a1; o[blk][nt][3] *= a1;
            }
        }

        // O += P V : V fragments loaded once, used by both row-blocks
#pragma unroll
        for (int kc = 0; kc < 4; kc++) {
            uint32_t ap0[4] = {ph[0][kc * 2][0], ph[0][kc * 2][1],
                               ph[0][kc * 2 + 1][0], ph[0][kc * 2 + 1][1]};
            uint32_t ap1[4] = {ph[1][kc * 2][0], ph[1][kc * 2][1],
                               ph[1][kc * 2 + 1][0], ph[1][kc * 2 + 1][1]};
#pragma unroll
            for (int nb = 0; nb < 4; nb++) {
                uint32_t r4[4];
                int krow = kc * 16 + a_row;
                int nbyte = nb * 32 + a_kb;
                ldsm4t(r4, Vs + SW128(krow * 128 + nbyte));
                uint32_t b0[2] = {r4[0], r4[1]};
                uint32_t b1[2] = {r4[2], r4[3]};
                mma_f16(o[0][nb * 2], ap0, b0);
                mma_f16(o[0][nb * 2 + 1], ap0, b1);
                mma_f16(o[1][nb * 2], ap1, b0);
                mma_f16(o[1][nb * 2 + 1], ap1, b1);
            }
        }
    }

    // epilogue: normalize, write fp16 context [B,S,D]
#pragma unroll
    for (int blk = 0; blk < 2; blk++) {
        float i0 = 1.f / lr[blk][0], i1 = 1.f / lr[blk][1];
        int srow = qt * 128 + w32 + blk * 16 + g;
#pragma unroll
        for (int nt = 0; nt < 8; nt++) {
            int col = h * DK + nt * 8 + 2 * t;
            __half* c0 = &C[((size_t)b * S_SZ + srow) * D_SZ + col];
            *(uint32_t*)c0 = pack_h2(o[blk][nt][0] * i0, o[blk][nt][1] * i0);
            __half* c1 = &C[((size_t)b * S_SZ + srow + 8) * D_SZ + col];
            *(uint32_t*)c1 = pack_h2(o[blk][nt][2] * i1, o[blk][nt][3] * i1);
        }
    }
}

// ---------------------------------------------------------------------------
// Launch. Inputs: query, key, value, Wq, bq, Wk, bk, Wv, bv, Wo, bo
// ---------------------------------------------------------------------------
extern "C" void kernel_launch(void* const* d_in, const int* in_sizes, int n_in,
                              void* d_out, int out_size)
{
    const float* q  = (const float*)d_in[0];
    const float* k  = (const float*)d_in[1];
    const float* v  = (const float*)d_in[2];
    const float* Wq = (const float*)d_in[3];
    const float* bq = (const float*)d_in[4];
    const float* Wk = (const float*)d_in[5];
    const float* bk = (const float*)d_in[6];
    const float* Wv = (const float*)d_in[7];
    const float* bv = (const float*)d_in[8];
    const float* Wo = (const float*)d_in[9];
    const float* bo = (const float*)d_in[10];
    float* out = (float*)d_out;

    __half *gqkv, *gc;
    cudaGetSymbolAddress((void**)&gqkv, g_QKV);
    cudaGetSymbolAddress((void**)&gc, g_Ch);
    __half* gq = gqkv;
    __half* gk = gqkv + 4194304;
    __half* gv = gqkv + 2 * 4194304;

    const int SMEM_GEMM = 98304;   // 3 x 32KB
    const int SMEM_ATTN = 65536;   // Q 16KB + 3 x 16KB
    cudaFuncSetAttribute(gemm_qkv,
                         cudaFuncAttributeMaxDynamicSharedMemorySize, SMEM_GEMM);
    cudaFuncSetAttribute(gemm_o,
                         cudaFuncAttributeMaxDynamicSharedMemorySize, SMEM_GEMM);
    cudaFuncSetAttribute(flash_h,
                         cudaFuncAttributeMaxDynamicSharedMemorySize, SMEM_ATTN);
    cudaFuncSetAttribute(gemm_qkv,
                         cudaFuncAttributePreferredSharedMemoryCarveout, 100);
    cudaFuncSetAttribute(gemm_o,
                         cudaFuncAttributePreferredSharedMemoryCarveout, 100);
    cudaFuncSetAttribute(flash_h,
                         cudaFuncAttributePreferredSharedMemoryCarveout, 100);

    prep_half<<<dim3(4096, 7), 256>>>(q, k, v, Wq, Wk, Wv, Wo);

    dim3 gqkv_grid(D_SZ / 128, M_SZ / 128, 3);  // (8, 32, 3)
    gemm_qkv<<<gqkv_grid, 128, SMEM_GEMM>>>(bq, bk, bv);

    dim3 agrid(S_SZ / 128, H_SZ, B_SZ);         // (16, 16, 2)
    flash_h<<<agrid, 128, SMEM_ATTN>>>(gq, gk, gv, gc);

    dim3 go_grid(D_SZ / 128, M_SZ / 128);       // (8, 32)
    gemm_o<<<go_grid, 128, SMEM_GEMM>>>(bo, out);
}

// round 9
// speedup vs baseline: 8.7109x; 1.0290x over previous
#include <cuda_runtime.h>
#include <cuda_fp16.h>
#include <cstdint>

#define B_SZ 2
#define S_SZ 2048
#define D_SZ 1024
#define H_SZ 16
#define DK 64
#define M_SZ (B_SZ * S_SZ)

// Scratch (device globals; no runtime allocation allowed)
__device__ __half g_Ah[3][4194304];  // fp16 query,key,value
__device__ __half g_Wh[4][1048576]; // fp16 Wq,Wk,Wv,Wo
__device__ __half g_QKV[3][4194304]; // Q/K/V [B,H,S,dk] fp16 (Q pre-scaled)
__device__ __half g_Ch[4194304];     // attention output [B,S,D], fp16

// ---------------------------------------------------------------------------
// helpers
// ---------------------------------------------------------------------------
__device__ __forceinline__ uint32_t pack_h2(float lo, float hi) {
    uint32_t d;
    asm("cvt.rn.f16x2.f32 %0, %1, %2;" : "=r"(d) : "f"(hi), "f"(lo));
    return d;
}

__device__ __forceinline__ float ex2(float x) {
    float y;
    asm("ex2.approx.ftz.f32 %0, %1;" : "=f"(y) : "f"(x));
    return y;
}

__device__ __forceinline__ uint32_t hmax2(uint32_t a, uint32_t b) {
    uint32_t d;
    asm("max.f16x2 %0, %1, %2;" : "=r"(d) : "r"(a), "r"(b));
    return d;
}
__device__ __forceinline__ uint32_t hadd2(uint32_t a, uint32_t b) {
    uint32_t d;
    asm("add.f16x2 %0, %1, %2;" : "=r"(d) : "r"(a), "r"(b));
    return d;
}
__device__ __forceinline__ uint32_t hsub2(uint32_t a, uint32_t b) {
    uint32_t d;
    asm("sub.f16x2 %0, %1, %2;" : "=r"(d) : "r"(a), "r"(b));
    return d;
}
__device__ __forceinline__ uint32_t hex2(uint32_t a) {
    uint32_t d;
    asm("ex2.approx.f16x2 %0, %1;" : "=r"(d) : "r"(a));
    return d;
}
__device__ __forceinline__ float2 h2f2(uint32_t h) {
    __half2 hh = *reinterpret_cast<__half2*>(&h);
    return __half22float2(hh);
}

__device__ __forceinline__ void mma_f16(float c[4], const uint32_t a[4],
                                        const uint32_t b[2]) {
    asm volatile(
        "mma.sync.aligned.m16n8k16.row.col.f32.f16.f16.f32 "
        "{%0,%1,%2,%3}, {%4,%5,%6,%7}, {%8,%9}, {%0,%1,%2,%3};\n"
        : "+f"(c[0]), "+f"(c[1]), "+f"(c[2]), "+f"(c[3])
        : "r"(a[0]), "r"(a[1]), "r"(a[2]), "r"(a[3]), "r"(b[0]), "r"(b[1]));
}

// f16 accumulator variant: 2x tensor rate; D packed {row g pair},{row g+8 pair}
__device__ __forceinline__ void mma_f16a(uint32_t c[2], const uint32_t a[4],
                                         const uint32_t b[2]) {
    asm volatile(
        "mma.sync.aligned.m16n8k16.row.col.f16.f16.f16.f16 "
        "{%0,%1}, {%2,%3,%4,%5}, {%6,%7}, {%0,%1};\n"
        : "+r"(c[0]), "+r"(c[1])
        : "r"(a[0]), "r"(a[1]), "r"(a[2]), "r"(a[3]), "r"(b[0]), "r"(b[1]));
}

__device__ __forceinline__ void ldsm4(uint32_t r[4], uint32_t addr) {
    asm volatile(
        "ldmatrix.sync.aligned.m8n8.x4.shared.b16 {%0,%1,%2,%3}, [%4];"
        : "=r"(r[0]), "=r"(r[1]), "=r"(r[2]), "=r"(r[3]) : "r"(addr));
}
__device__ __forceinline__ void ldsm4t(uint32_t r[4], uint32_t addr) {
    asm volatile(
        "ldmatrix.sync.aligned.m8n8.x4.trans.shared.b16 {%0,%1,%2,%3}, [%4];"
        : "=r"(r[0]), "=r"(r[1]), "=r"(r[2]), "=r"(r[3]) : "r"(addr));
}

__device__ __forceinline__ void cp16(uint32_t dst, const void* src) {
    asm volatile("cp.async.cg.shared.global [%0], [%1], 16;\n"
                 :: "r"(dst), "l"(src));
}
__device__ __forceinline__ void cp_commit() {
    asm volatile("cp.async.commit_group;\n");
}
template <int N> __device__ __forceinline__ void cp_wait() {
    asm volatile("cp.async.wait_group %0;\n" :: "n"(N));
}

#define SW128(off) ((off) ^ (((off) >> 3) & 0x70))

// ---------------------------------------------------------------------------
// Prep: convert all GEMM inputs to fp16 once.
// ---------------------------------------------------------------------------
__global__ void prep_half(
    const float* __restrict__ q, const float* __restrict__ k,
    const float* __restrict__ v, const float* __restrict__ w0,
    const float* __restrict__ w1, const float* __restrict__ w2,
    const float* __restrict__ w3)
{
    const int a = blockIdx.y;
    const float* src;
    __half* dst;
    int n4;
    switch (a) {
        case 0: src = q;  dst = g_Ah[0]; n4 = 1048576; break;
        case 1: src = k;  dst = g_Ah[1]; n4 = 1048576; break;
        case 2: src = v;  dst = g_Ah[2]; n4 = 1048576; break;
        case 3: src = w0; dst = g_Wh[0]; n4 = 262144; break;
        case 4: src = w1; dst = g_Wh[1]; n4 = 262144; break;
        case 5: src = w2; dst = g_Wh[2]; n4 = 262144; break;
        default: src = w3; dst = g_Wh[3]; n4 = 262144; break;
    }
    int i = blockIdx.x * blockDim.x + threadIdx.x;
    if (i >= n4) return;
    float4 t4 = ((const float4*)src)[i];
    uint2 u = {pack_h2(t4.x, t4.y), pack_h2(t4.z, t4.w)};
    ((uint2*)dst)[i] = u;
}

// ---------------------------------------------------------------------------
// GEMM core (unchanged from R8): CTA 128x128, 4 warps 64x64, BK=64,
// 3-stage cp.async. f32 accumulators (precision for K=1024).
// ---------------------------------------------------------------------------
__device__ __forceinline__ void gemm_core(
    const __half* __restrict__ A, const __half* __restrict__ W,
    const float* __restrict__ bias, __half* __restrict__ outh,
    float* __restrict__ outf, float scale, int mode, char* smraw)
{
    uint32_t smb = (uint32_t)__cvta_generic_to_shared(smraw);

    const int tid = threadIdx.x, lane = tid & 31, wid = tid >> 5;
    const int g = lane >> 2, t = lane & 3;
    const int warpM = wid & 1, warpN = wid >> 1;
    const int m0 = blockIdx.y * 128, n0 = blockIdx.x * 128;

    float acc[4][8][4] = {};

    const int a_row = (lane & 7) + ((lane >> 3) & 1) * 8;
    const int a_kb = ((lane >> 4) & 1) * 16;
    const int b_row = (lane & 7) + ((lane >> 4) & 1) * 8;
    const int b_kb = ((lane >> 3) & 1) * 16;

    auto fill = [&](int buf, int kt) {
        uint32_t ab = smb + buf * 32768;
        uint32_t bb = ab + 16384;
        const __half* As = A + (size_t)m0 * D_SZ + kt * 64;
        const __half* Ws = W + (size_t)n0 * D_SZ + kt * 64;
#pragma unroll
        for (int i = 0; i < 8; i++) {
            int ch = i * 128 + tid;
            int r = ch >> 3;
            int cb = (ch & 7) * 16;
            uint32_t sw = SW128(r * 128 + cb);
            cp16(ab + sw, (const char*)(As + (size_t)r * D_SZ) + cb);
            cp16(bb + sw, (const char*)(Ws + (size_t)r * D_SZ) + cb);
        }
        cp_commit();
    };

    fill(0, 0);
    fill(1, 1);
    int buf = 0, fbuf = 2;
    for (int kb = 0; kb < 16; kb++) {
        if (kb == 15) cp_wait<0>(); else cp_wait<1>();
        __syncthreads();
        if (kb + 2 < 16) {
            fill(fbuf, kb + 2);
            fbuf = (fbuf == 2) ? 0 : fbuf + 1;
        }
        uint32_t ab = smb + buf * 32768;
        uint32_t bb = ab + 16384;
#pragma unroll
        for (int ks = 0; ks < 4; ks++) {
            uint32_t af[4][4], bf[8][2];
#pragma unroll
            for (int mt = 0; mt < 4; mt++) {
                int row = warpM * 64 + mt * 16 + a_row;
                ldsm4(af[mt], ab + SW128(row * 128 + ks * 32 + a_kb));
            }
#pragma unroll
            for (int nb = 0; nb < 4; nb++) {
                uint32_t r4[4];
                int row = warpN * 64 + nb * 16 + b_row;
                ldsm4(r4, bb + SW128(row * 128 + ks * 32 + b_kb));
                bf[nb * 2][0] = r4[0]; bf[nb * 2][1] = r4[1];
                bf[nb * 2 + 1][0] = r4[2]; bf[nb * 2 + 1][1] = r4[3];
            }
#pragma unroll
            for (int mt = 0; mt < 4; mt++)
#pragma unroll
                for (int nt = 0; nt < 8; nt++)
                    mma_f16(acc[mt][nt], af[mt], bf[nt]);
        }
        buf = (buf == 2) ? 0 : buf + 1;
    }

    // epilogue
#pragma unroll
    for (int mt = 0; mt < 4; mt++) {
#pragma unroll
        for (int nt = 0; nt < 8; nt++) {
            int col = n0 + warpN * 64 + nt * 8 + 2 * t;
            float b0 = bias[col], b1 = bias[col + 1];
            int r0 = m0 + warpM * 64 + mt * 16 + g;
            float v00 = (acc[mt][nt][0] + b0) * scale;
            float v01 = (acc[mt][nt][1] + b1) * scale;
            float v10 = (acc[mt][nt][2] + b0) * scale;
            float v11 = (acc[mt][nt][3] + b1) * scale;
            if (mode) {
                int hh = col >> 6, dh = col & 63;
                int bb0 = r0 >> 11, s0 = r0 & 2047;
                __half* p0 = &outh[(((size_t)(bb0 * H_SZ + hh)) * S_SZ + s0) * DK + dh];
                *(uint32_t*)p0 = pack_h2(v00, v01);
                int r1 = r0 + 8;
                int bb1 = r1 >> 11, s1 = r1 & 2047;
                __half* p1 = &outh[(((size_t)(bb1 * H_SZ + hh)) * S_SZ + s1) * DK + dh];
                *(uint32_t*)p1 = pack_h2(v10, v11);
            } else {
                *(float2*)&outf[(size_t)r0 * D_SZ + col] = make_float2(v00, v01);
                *(float2*)&outf[(size_t)(r0 + 8) * D_SZ + col] = make_float2(v10, v11);
            }
        }
    }
}

// Fused Q/K/V projections: blockIdx.z selects input/weight/output set.
__global__ __launch_bounds__(128) void gemm_qkv(
    const float* __restrict__ bq, const float* __restrict__ bk,
    const float* __restrict__ bv)
{
    extern __shared__ char smraw[];
    const int z = blockIdx.z;
    const float* bias = (z == 0) ? bq : (z == 1) ? bk : bv;
    const float scale = (z == 0) ? 0.125f * 1.4426950408889634f : 1.0f;
    gemm_core(g_Ah[z], g_Wh[z], bias, g_QKV[z], nullptr, scale, 1, smraw);
}

// Output projection: fp16 context @ Wo^T + bo -> f32 out
__global__ __launch_bounds__(128) void gemm_o(
    const float* __restrict__ bo, float* __restrict__ out)
{
    extern __shared__ char smraw[];
    gemm_core(g_Ch, g_Wh[3], bo, nullptr, out, 1.0f, 0, smraw);
}

// ---------------------------------------------------------------------------
// Flash attention. CTA = 128 queries, 4 warps x 32 rows (2 row-blocks).
// S = QK^T in f16-accumulator mma (2x tensor rate; dk=64 reduction is safe).
// Packed-h2 softmax: max.f16x2 / sub+ex2.f16x2 / add.f16x2 trees.
// S D-fragment == P A-fragment layout -> zero repacking. PV stays f32-accum.
// ---------------------------------------------------------------------------
__global__ __launch_bounds__(128) void flash_h(
    const __half* __restrict__ Q, const __half* __restrict__ K,
    const __half* __restrict__ V, __half* __restrict__ C)
{
    extern __shared__ char smraw[];
    uint32_t smb = (uint32_t)__cvta_generic_to_shared(smraw);
    const uint32_t Qb_s = smb;

    const int tid = threadIdx.x, lane = tid & 31, wid = tid >> 5;
    const int g = lane >> 2, t = lane & 3;
    const int w32 = wid * 32;
    const int qt = blockIdx.x, h = blockIdx.y, b = blockIdx.z;

    const size_t hoff = ((size_t)(b * H_SZ + h)) * S_SZ * DK;
    const __half* Qg = Q + hoff + (size_t)qt * 128 * DK;
    const __half* Kg = K + hoff;
    const __half* Vg = V + hoff;

    const int a_row = (lane & 7) + ((lane >> 3) & 1) * 8;
    const int a_kb = ((lane >> 4) & 1) * 16;
    const int b_row = (lane & 7) + ((lane >> 4) & 1) * 8;
    const int b_kb = ((lane >> 3) & 1) * 16;

    // Stage Q (128 x 64 halves = 128B rows)
#pragma unroll
    for (int i = 0; i < 8; i++) {
        int ch = i * 128 + tid;
        int r = ch >> 3, cb = (ch & 7) * 16;
        cp16(Qb_s + SW128(r * 128 + cb), (const char*)(Qg + (size_t)r * DK) + cb);
    }
    cp_commit();

    auto fillKV = [&](int buf, int kt) {
        uint32_t kd = smb + 16384 + buf * 16384;
        uint32_t vd = kd + 8192;
        const __half* Kp = Kg + (size_t)kt * 64 * DK;
        const __half* Vp = Vg + (size_t)kt * 64 * DK;
#pragma unroll
        for (int i = 0; i < 4; i++) {
            int ch = i * 128 + tid;
            int r = ch >> 3, cb = (ch & 7) * 16;
            uint32_t sw = SW128(r * 128 + cb);
            cp16(kd + sw, (const char*)(Kp + (size_t)r * DK) + cb);
            cp16(vd + sw, (const char*)(Vp + (size_t)r * DK) + cb);
        }
        cp_commit();
    };

    fillKV(0, 0);
    fillKV(1, 1);
    cp_wait<2>();   // Q landed
    __syncthreads();

    // Q fragments: 2 row-blocks x 4 k16 chunks
    uint32_t qf[2][4][4];
#pragma unroll
    for (int blk = 0; blk < 2; blk++)
#pragma unroll
        for (int ks = 0; ks < 4; ks++) {
            int row = w32 + blk * 16 + a_row;
            ldsm4(qf[blk][ks], Qb_s + SW128(row * 128 + ks * 32 + a_kb));
        }

    float o[2][8][4] = {};
    float mr[2][2] = {{-30000.f, -30000.f}, {-30000.f, -30000.f}};
    float lr[2][2] = {{0.f, 0.f}, {0.f, 0.f}};

    int buf = 0, fbuf = 2;
    const int NT = S_SZ / 64;  // 32
    for (int kt = 0; kt < NT; kt++) {
        if (kt == NT - 1) cp_wait<0>(); else cp_wait<1>();
        __syncthreads();
        if (kt + 2 < NT) {
            fillKV(fbuf, kt + 2);
            fbuf = (fbuf == 2) ? 0 : fbuf + 1;
        }

        uint32_t Ks = smb + 16384 + buf * 16384;
        uint32_t Vs = Ks + 8192;
        buf = (buf == 2) ? 0 : buf + 1;

        // S = Q K^T in f16 accum: sh[blk][nt] = {row g pair, row g+8 pair}
        uint32_t sh[2][8][2] = {};
#pragma unroll
        for (int ks = 0; ks < 4; ks++) {
#pragma unroll
            for (int nb = 0; nb < 4; nb++) {
                uint32_t r4[4];
                int row = nb * 16 + b_row;
                ldsm4(r4, Ks + SW128(row * 128 + ks * 32 + b_kb));
                uint32_t b0[2] = {r4[0], r4[1]};
                uint32_t b1[2] = {r4[2], r4[3]};
#pragma unroll
                for (int blk = 0; blk < 2; blk++) {
                    mma_f16a(sh[blk][nb * 2], qf[blk][ks], b0);
                    mma_f16a(sh[blk][nb * 2 + 1], qf[blk][ks], b1);
                }
            }
        }

        // packed online softmax per block (rows g, g+8)
#pragma unroll
        for (int blk = 0; blk < 2; blk++) {
            // row-max trees (packed)
            uint32_t mx0 = hmax2(hmax2(hmax2(sh[blk][0][0], sh[blk][1][0]),
                                       hmax2(sh[blk][2][0], sh[blk][3][0])),
                                 hmax2(hmax2(sh[blk][4][0], sh[blk][5][0]),
                                       hmax2(sh[blk][6][0], sh[blk][7][0])));
            uint32_t mx1 = hmax2(hmax2(hmax2(sh[blk][0][1], sh[blk][1][1]),
                                       hmax2(sh[blk][2][1], sh[blk][3][1])),
                                 hmax2(hmax2(sh[blk][4][1], sh[blk][5][1]),
                                       hmax2(sh[blk][6][1], sh[blk][7][1])));
            float2 f0 = h2f2(mx0), f1 = h2f2(mx1);
            float ml0 = fmaxf(f0.x, f0.y), ml1 = fmaxf(f1.x, f1.y);
            ml0 = fmaxf(ml0, __shfl_xor_sync(~0u, ml0, 1));
            ml0 = fmaxf(ml0, __shfl_xor_sync(~0u, ml0, 2));
            ml1 = fmaxf(ml1, __shfl_xor_sync(~0u, ml1, 1));
            ml1 = fmaxf(ml1, __shfl_xor_sync(~0u, ml1, 2));
            float mn0 = fmaxf(mr[blk][0], ml0), mn1 = fmaxf(mr[blk][1], ml1);
            float a0 = ex2(mr[blk][0] - mn0), a1 = ex2(mr[blk][1] - mn1);
            mr[blk][0] = mn0;
            mr[blk][1] = mn1;
            uint32_t mn0h = pack_h2(mn0, mn0), mn1h = pack_h2(mn1, mn1);
            // P = ex2(S - mn) in packed f16 (already A-fragment layout)
#pragma unroll
            for (int nt = 0; nt < 8; nt++) {
                sh[blk][nt][0] = hex2(hsub2(sh[blk][nt][0], mn0h));
                sh[blk][nt][1] = hex2(hsub2(sh[blk][nt][1], mn1h));
            }
            // row-sum trees (packed; max 8 per half-lane, exact-ish in f16)
            uint32_t t0 = hadd2(hadd2(hadd2(sh[blk][0][0], sh[blk][1][0]),
                                      hadd2(sh[blk][2][0], sh[blk][3][0])),
                                hadd2(hadd2(sh[blk][4][0], sh[blk][5][0]),
                                      hadd2(sh[blk][6][0], sh[blk][7][0])));
            uint32_t t1 = hadd2(hadd2(hadd2(sh[blk][0][1], sh[blk][1][1]),
                                      hadd2(sh[blk][2][1], sh[blk][3][1])),
                                hadd2(hadd2(sh[blk][4][1], sh[blk][5][1]),
                                      hadd2(sh[blk][6][1], sh[blk][7][1])));
            float2 r0 = h2f2(t0), r1 = h2f2(t1);
            float rs0 = r0.x + r0.y, rs1 = r1.x + r1.y;
            rs0 += __shfl_xor_sync(~0u, rs0, 1);
            rs0 += __shfl_xor_sync(~0u, rs0, 2);
            rs1 += __shfl_xor_sync(~0u, rs1, 1);
            rs1 += __shfl_xor_sync(~0u, rs1, 2);
            lr[blk][0] = lr[blk][0] * a0 + rs0;
            lr[blk][1] = lr[blk][1] * a1 + rs1;
#pragma unroll
            for (int nt = 0; nt < 8; nt++) {
                o[blk][nt][0] *= a0; o[blk][nt][1] *= a0;
                o[blk][nt][2] *= a1; o[blk][nt][3] *= a1;
            }
        }

        // O += P V : V fragments loaded once, shared across row-blocks.
        // P A-fragments come straight from sh (layout identity).
#pragma unroll
        for (int kc = 0; kc < 4; kc++) {
            uint32_t ap0[4] = {sh[0][kc * 2][0], sh[0][kc * 2][1],
                               sh[0][kc * 2 + 1][0], sh[0][kc * 2 + 1][1]};
            uint32_t ap1[4] = {sh[1][kc * 2][0], sh[1][kc * 2][1],
                               sh[1][kc * 2 + 1][0], sh[1][kc * 2 + 1][1]};
#pragma unroll
            for (int nb = 0; nb < 4; nb++) {
                uint32_t r4[4];
                int krow = kc * 16 + a_row;
                int nbyte = nb * 32 + a_kb;
                ldsm4t(r4, Vs + SW128(krow * 128 + nbyte));
                uint32_t b0[2] = {r4[0], r4[1]};
                uint32_t b1[2] = {r4[2], r4[3]};
                mma_f16(o[0][nb * 2], ap0, b0);
                mma_f16(o[0][nb * 2 + 1], ap0, b1);
                mma_f16(o[1][nb * 2], ap1, b0);
                mma_f16(o[1][nb * 2 + 1], ap1, b1);
            }
        }
    }

    // epilogue: normalize, write fp16 context [B,S,D]
#pragma unroll
    for (int blk = 0; blk < 2; blk++) {
        float i0 = 1.f / lr[blk][0], i1 = 1.f / lr[blk][1];
        int srow = qt * 128 + w32 + blk * 16 + g;
#pragma unroll
        for (int nt = 0; nt < 8; nt++) {
            int col = h * DK + nt * 8 + 2 * t;
            __half* c0 = &C[((size_t)b * S_SZ + srow) * D_SZ + col];
            *(uint32_t*)c0 = pack_h2(o[blk][nt][0] * i0, o[blk][nt][1] * i0);
            __half* c1 = &C[((size_t)b * S_SZ + srow + 8) * D_SZ + col];
            *(uint32_t*)c1 = pack_h2(o[blk][nt][2] * i1, o[blk][nt][3] * i1);
        }
    }
}

// ---------------------------------------------------------------------------
// Launch. Inputs: query, key, value, Wq, bq, Wk, bk, Wv, bv, Wo, bo
// ---------------------------------------------------------------------------
extern "C" void kernel_launch(void* const* d_in, const int* in_sizes, int n_in,
                              void* d_out, int out_size)
{
    const float* q  = (const float*)d_in[0];
    const float* k  = (const float*)d_in[1];
    const float* v  = (const float*)d_in[2];
    const float* Wq = (const float*)d_in[3];
    const float* bq = (const float*)d_in[4];
    const float* Wk = (const float*)d_in[5];
    const float* bk = (const float*)d_in[6];
    const float* Wv = (const float*)d_in[7];
    const float* bv = (const float*)d_in[8];
    const float* Wo = (const float*)d_in[9];
    const float* bo = (const float*)d_in[10];
    float* out = (float*)d_out;

    __half *gqkv, *gc;
    cudaGetSymbolAddress((void**)&gqkv, g_QKV);
    cudaGetSymbolAddress((void**)&gc, g_Ch);
    __half* gq = gqkv;
    __half* gk = gqkv + 4194304;
    __half* gv = gqkv + 2 * 4194304;

    const int SMEM_GEMM = 98304;   // 3 x 32KB
    const int SMEM_ATTN = 65536;   // Q 16KB + 3 x 16KB
    cudaFuncSetAttribute(gemm_qkv,
                         cudaFuncAttributeMaxDynamicSharedMemorySize, SMEM_GEMM);
    cudaFuncSetAttribute(gemm_o,
                         cudaFuncAttributeMaxDynamicSharedMemorySize, SMEM_GEMM);
    cudaFuncSetAttribute(flash_h,
                         cudaFuncAttributeMaxDynamicSharedMemorySize, SMEM_ATTN);
    cudaFuncSetAttribute(gemm_qkv,
                         cudaFuncAttributePreferredSharedMemoryCarveout, 100);
    cudaFuncSetAttribute(gemm_o,
                         cudaFuncAttributePreferredSharedMemoryCarveout, 100);
    cudaFuncSetAttribute(flash_h,
                         cudaFuncAttributePreferredSharedMemoryCarveout, 100);

    prep_half<<<dim3(4096, 7), 256>>>(q, k, v, Wq, Wk, Wv, Wo);

    dim3 gqkv_grid(D_SZ / 128, M_SZ / 128, 3);  // (8, 32, 3)
    gemm_qkv<<<gqkv_grid, 128, SMEM_GEMM>>>(bq, bk, bv);

    dim3 agrid(S_SZ / 128, H_SZ, B_SZ);         // (16, 16, 2)
    flash_h<<<agrid, 128, SMEM_ATTN>>>(gq, gk, gv, gc);

    dim3 go_grid(D_SZ / 128, M_SZ / 128);       // (8, 32)
    gemm_o<<<go_grid, 128, SMEM_GEMM>>>(bo, out);
}